// round 4
// baseline (speedup 1.0000x reference)
#include <cuda_runtime.h>

// Problem constants
#define BATCH   2
#define S_LEN   2048
#define DMODEL  1024
#define NHEADS  16
#define HD      64
#define BHTOT   (BATCH * NHEADS)          // 32
#define M_ROWS  (BATCH * S_LEN)           // 4096
#define HEAD_STRIDE  (S_LEN * HD)         // 131072
#define BATCH_STRIDE (NHEADS * S_LEN * HD)

// Scratch: [B, H, S, hd] fp32 layouts (16 MB each)
__device__ float g_q[BHTOT * S_LEN * HD];
__device__ float g_k[BHTOT * S_LEN * HD];
__device__ float g_v[BHTOT * S_LEN * HD];
__device__ float g_ctx[BHTOT * S_LEN * HD];

// ---------------------------------------------------------------------------
// Register-tiled SGEMM: C[M,N] = A[M,K] * B[N,K]^T + bias[N]
// BM=BN=128, BK=8, 256 threads, 8x8 per thread.
// GATHER_A: A rows gathered from g_ctx [B,H,S,hd] (k -> (h=k/64, d=k%64))
// SCATTER_C: C written into [B,H,S,hd] layout (n -> (h=n/64, d=n%64))
// ---------------------------------------------------------------------------
#define BM 128
#define BN 128
#define BK 8
#define GP (BM + 4)   // padded smem row -> conflict-free transpose stores

template <bool GATHER_A, bool SCATTER_C>
__device__ __forceinline__ void gemm_body(
    const float* __restrict__ A, const float* __restrict__ B,
    const float* __restrict__ bias, float* __restrict__ C)
{
    __shared__ float As[BK][GP];
    __shared__ float Bs[BK][GP];

    const int tid  = threadIdx.x;
    const int tx   = tid & 15;
    const int ty   = tid >> 4;
    const int row0 = blockIdx.y * BM;
    const int col0 = blockIdx.x * BN;

    const int lr = tid >> 1;        // 0..127 : tile row loaded by this thread
    const int lc = (tid & 1) * 4;   // 0 or 4 : k-offset within BK

    const int K = DMODEL;

    float acc[8][8];
#pragma unroll
    for (int i = 0; i < 8; i++)
#pragma unroll
        for (int j = 0; j < 8; j++) acc[i][j] = 0.0f;

    const int m = row0 + lr;
    const float* Bptr = B + (size_t)(col0 + lr) * K + lc;
    const float* Aptr = nullptr;
    size_t abase = 0;
    if (GATHER_A) {
        abase = (size_t)(m >> 11) * BATCH_STRIDE + (size_t)(m & (S_LEN - 1)) * HD;
    } else {
        Aptr = A + (size_t)m * K + lc;
    }

    for (int k0 = 0; k0 < K; k0 += BK) {
        float4 av, bv;
        if (GATHER_A) {
            int k = k0 + lc;   // k..k+3 stay within one head (BK=8 | 64)
            av = *(const float4*)(A + abase + (size_t)(k >> 6) * HEAD_STRIDE + (k & 63));
        } else {
            av = *(const float4*)(Aptr + k0);
        }
        bv = *(const float4*)(Bptr + k0);

        __syncthreads();
        As[lc + 0][lr] = av.x; As[lc + 1][lr] = av.y;
        As[lc + 2][lr] = av.z; As[lc + 3][lr] = av.w;
        Bs[lc + 0][lr] = bv.x; Bs[lc + 1][lr] = bv.y;
        Bs[lc + 2][lr] = bv.z; Bs[lc + 3][lr] = bv.w;
        __syncthreads();

#pragma unroll
        for (int kk = 0; kk < BK; kk++) {
            float ar[8], br[8];
            *(float4*)&ar[0] = *(const float4*)&As[kk][ty * 8];
            *(float4*)&ar[4] = *(const float4*)&As[kk][ty * 8 + 4];
            *(float4*)&br[0] = *(const float4*)&Bs[kk][tx * 8];
            *(float4*)&br[4] = *(const float4*)&Bs[kk][tx * 8 + 4];
#pragma unroll
            for (int i = 0; i < 8; i++)
#pragma unroll
                for (int j = 0; j < 8; j++)
                    acc[i][j] += ar[i] * br[j];
        }
    }

    // Epilogue: bias + store
#pragma unroll
    for (int i = 0; i < 8; i++) {
        const int m2 = row0 + ty * 8 + i;
#pragma unroll
        for (int j4 = 0; j4 < 8; j4 += 4) {
            const int n = col0 + tx * 8 + j4;
            float4 r;
            r.x = acc[i][j4 + 0] + bias[n + 0];
            r.y = acc[i][j4 + 1] + bias[n + 1];
            r.z = acc[i][j4 + 2] + bias[n + 2];
            r.w = acc[i][j4 + 3] + bias[n + 3];
            if (SCATTER_C) {
                size_t o = (size_t)((m2 >> 11) * NHEADS + (n >> 6)) * HEAD_STRIDE
                         + (size_t)(m2 & (S_LEN - 1)) * HD + (n & 63);
                *(float4*)(C + o) = r;
            } else {
                *(float4*)(C + (size_t)m2 * DMODEL + n) = r;
            }
        }
    }
}

__global__ __launch_bounds__(256, 2) void qkv_gemm_kernel(
    const float* __restrict__ X,
    const float* __restrict__ Wq, const float* __restrict__ Wk, const float* __restrict__ Wv,
    const float* __restrict__ bq, const float* __restrict__ bk, const float* __restrict__ bv)
{
    const float* W;  const float* b;  float* out;
    if (blockIdx.z == 0)      { W = Wq; b = bq; out = g_q; }
    else if (blockIdx.z == 1) { W = Wk; b = bk; out = g_k; }
    else                      { W = Wv; b = bv; out = g_v; }
    gemm_body<false, true>(X, W, b, out);
}

__global__ __launch_bounds__(256, 2) void out_gemm_kernel(
    const float* __restrict__ Wo, const float* __restrict__ bo, float* __restrict__ out)
{
    gemm_body<true, false>(g_ctx, Wo, bo, out);
}

// ---------------------------------------------------------------------------
// Flash attention, causal. One CTA = 64 queries of one (b,h).
// 256 threads as 16x16; each thread owns a 4x4 tile of S and of O.
// Row group (fixed ty) = 16 consecutive lanes -> half-warp shfl reductions.
// smem: Qs/Ks transposed [d][row] (padded to 68), Ps [c][row], Vs [c][d].
// ---------------------------------------------------------------------------
#define QPAD 68
#define ATTN_SMEM ((3 * 64 * QPAD + 64 * 64) * 4)

__global__ __launch_bounds__(256) void attn_kernel()
{
    extern __shared__ float smem[];
    float* qsm = smem;                  // 64 x 68   [d][r], pre-scaled by 1/8
    float* ksm = qsm + 64 * QPAD;       // 64 x 68   [d][c]
    float* psm = ksm + 64 * QPAD;       // 64 x 68   [c][r]
    float* vsm = psm + 64 * QPAD;       // 64 x 64   [c][d]

    const int tid = threadIdx.x;
    const int tx  = tid & 15;
    const int ty  = tid >> 4;
    const int qb  = blockIdx.x;
    const int bh  = blockIdx.y;

    const size_t base = (size_t)bh * HEAD_STRIDE;
    const float* Qg = g_q + base + (size_t)qb * 64 * HD;
    const float* Kg = g_k + base;
    const float* Vg = g_v + base;
    float*       Og = g_ctx + base + (size_t)qb * 64 * HD;

    // Load Q tile transposed + scaled (once)
#pragma unroll
    for (int i = 0; i < 4; i++) {
        int idx = i * 1024 + tid * 4;
        int r = idx >> 6, d = idx & 63;
        float4 q4 = *(const float4*)(Qg + idx);
        qsm[(d + 0) * QPAD + r] = q4.x * 0.125f;
        qsm[(d + 1) * QPAD + r] = q4.y * 0.125f;
        qsm[(d + 2) * QPAD + r] = q4.z * 0.125f;
        qsm[(d + 3) * QPAD + r] = q4.w * 0.125f;
    }

    float accO[4][4];
#pragma unroll
    for (int i = 0; i < 4; i++)
#pragma unroll
        for (int j = 0; j < 4; j++) accO[i][j] = 0.0f;
    float m_i[4], l_i[4];
#pragma unroll
    for (int i = 0; i < 4; i++) { m_i[i] = -1e30f; l_i[i] = 0.0f; }

    for (int kb = 0; kb <= qb; kb++) {
        __syncthreads();   // prev iteration done reading Ks/Vs/Ps
        const float* Kt = Kg + (size_t)kb * 64 * HD;
        const float* Vt = Vg + (size_t)kb * 64 * HD;
#pragma unroll
        for (int i = 0; i < 4; i++) {
            int idx = i * 1024 + tid * 4;
            int r = idx >> 6, d = idx & 63;
            float4 k4 = *(const float4*)(Kt + idx);
            ksm[(d + 0) * QPAD + r] = k4.x;
            ksm[(d + 1) * QPAD + r] = k4.y;
            ksm[(d + 2) * QPAD + r] = k4.z;
            ksm[(d + 3) * QPAD + r] = k4.w;
            float4 v4 = *(const float4*)(Vt + idx);
            *(float4*)(vsm + idx) = v4;      // [c][d] direct
        }
        __syncthreads();

        // S = Q K^T  (scaled Q)
        float s4[4][4];
#pragma unroll
        for (int i = 0; i < 4; i++)
#pragma unroll
            for (int j = 0; j < 4; j++) s4[i][j] = 0.0f;
#pragma unroll 16
        for (int d = 0; d < 64; d++) {
            float4 qv = *(const float4*)(qsm + d * QPAD + ty * 4);
            float4 kv = *(const float4*)(ksm + d * QPAD + tx * 4);
            float qa[4] = {qv.x, qv.y, qv.z, qv.w};
            float ka[4] = {kv.x, kv.y, kv.z, kv.w};
#pragma unroll
            for (int ii = 0; ii < 4; ii++)
#pragma unroll
                for (int jj = 0; jj < 4; jj++)
                    s4[ii][jj] += qa[ii] * ka[jj];
        }

        if (kb == qb) {   // diagonal tile: causal mask
#pragma unroll
            for (int ii = 0; ii < 4; ii++)
#pragma unroll
                for (int jj = 0; jj < 4; jj++)
                    if (tx * 4 + jj > ty * 4 + ii) s4[ii][jj] = -1e30f;
        }

        // Online softmax: half-warp reductions (row group = 16 lanes)
        float newm[4], alpha[4], psum[4];
#pragma unroll
        for (int ii = 0; ii < 4; ii++) {
            float mx = fmaxf(fmaxf(s4[ii][0], s4[ii][1]), fmaxf(s4[ii][2], s4[ii][3]));
#pragma unroll
            for (int off = 1; off < 16; off <<= 1)
                mx = fmaxf(mx, __shfl_xor_sync(0xffffffffu, mx, off));
            mx = fmaxf(mx, m_i[ii]);
            newm[ii]  = mx;
            alpha[ii] = __expf(m_i[ii] - mx);
            float ps = 0.0f;
#pragma unroll
            for (int jj = 0; jj < 4; jj++) {
                float p = __expf(s4[ii][jj] - mx);
                ps += p;
                psm[(tx * 4 + jj) * QPAD + ty * 4 + ii] = p;
            }
#pragma unroll
            for (int off = 1; off < 16; off <<= 1)
                ps += __shfl_xor_sync(0xffffffffu, ps, off);
            psum[ii] = ps;
        }
        __syncthreads();   // Ps visible to all

#pragma unroll
        for (int ii = 0; ii < 4; ii++) {
            l_i[ii] = l_i[ii] * alpha[ii] + psum[ii];
            m_i[ii] = newm[ii];
#pragma unroll
            for (int jj = 0; jj < 4; jj++) accO[ii][jj] *= alpha[ii];
        }

        // O += P @ V
#pragma unroll 16
        for (int c = 0; c < 64; c++) {
            float4 pv = *(const float4*)(psm + c * QPAD + ty * 4);
            float4 vv = *(const float4*)(vsm + c * 64 + tx * 4);
            float pa[4] = {pv.x, pv.y, pv.z, pv.w};
            float va[4] = {vv.x, vv.y, vv.z, vv.w};
#pragma unroll
            for (int ii = 0; ii < 4; ii++)
#pragma unroll
                for (int jj = 0; jj < 4; jj++)
                    accO[ii][jj] += pa[ii] * va[jj];
        }
    }

    // Epilogue: normalize and write ctx [B,H,S,hd]
#pragma unroll
    for (int ii = 0; ii < 4; ii++) {
        float inv = 1.0f / l_i[ii];
        float4 r;
        r.x = accO[ii][0] * inv;
        r.y = accO[ii][1] * inv;
        r.z = accO[ii][2] * inv;
        r.w = accO[ii][3] * inv;
        *(float4*)(Og + (size_t)(ty * 4 + ii) * HD + tx * 4) = r;
    }
}

// ---------------------------------------------------------------------------
extern "C" void kernel_launch(void* const* d_in, const int* in_sizes, int n_in,
                              void* d_out, int out_size)
{
    (void)in_sizes; (void)n_in; (void)out_size;
    const float* x  = (const float*)d_in[0];
    const float* Wq = (const float*)d_in[1];
    const float* bq = (const float*)d_in[2];
    const float* Wk = (const float*)d_in[3];
    const float* bk = (const float*)d_in[4];
    const float* Wv = (const float*)d_in[5];
    const float* bv = (const float*)d_in[6];
    const float* Wo = (const float*)d_in[7];
    const float* bo = (const float*)d_in[8];
    float* out = (float*)d_out;

    // Host-side attribute set (not a stream op; capture-safe, idempotent)
    cudaFuncSetAttribute(attn_kernel,
                         cudaFuncAttributeMaxDynamicSharedMemorySize, ATTN_SMEM);

    dim3 blk(256);
    // 1) QKV projections -> g_q/g_k/g_v in [B,H,S,hd]
    qkv_gemm_kernel<<<dim3(DMODEL / BN, M_ROWS / BM, 3), blk>>>(x, Wq, Wk, Wv, bq, bk, bv);
    // 2) Causal flash attention -> g_ctx
    attn_kernel<<<dim3(S_LEN / 64, BHTOT), blk, ATTN_SMEM>>>();
    // 3) Output projection -> d_out
    out_gemm_kernel<<<dim3(DMODEL / BN, M_ROWS / BM), blk>>>(Wo, bo, out);
}

// round 6
// speedup vs baseline: 5.4065x; 5.4065x over previous
#include <cuda_runtime.h>
#include <cstdint>

// ---------------------------------------------------------------------------
// Problem constants
// ---------------------------------------------------------------------------
#define BATCH   2
#define S_LEN   2048
#define DMODEL  1024
#define NHEADS  16
#define HD      64
#define BHTOT   (BATCH * NHEADS)          // 32
#define M_ROWS  (BATCH * S_LEN)           // 4096
#define HEAD_STRIDE  (S_LEN * HD)         // 131072
#define BATCH_STRIDE (NHEADS * S_LEN * HD)

// Scratch (device globals; no allocations allowed)
__device__ float g_q  [BHTOT * S_LEN * HD];
__device__ float g_k  [BHTOT * S_LEN * HD];
__device__ float g_v  [BHTOT * S_LEN * HD];
__device__ float g_ctx[BHTOT * S_LEN * HD];
__device__ float g_xr [M_ROWS * DMODEL];          // tf32-rounded x
__device__ float g_wr [4][DMODEL * DMODEL];       // tf32-rounded Wq,Wk,Wv,Wo

// ---------------------------------------------------------------------------
// Helpers
// ---------------------------------------------------------------------------
__device__ __forceinline__ float rna_tf32(float v) {
    uint32_t o;
    asm("cvt.rna.tf32.f32 %0, %1;" : "=r"(o) : "f"(v));
    return __uint_as_float(o);
}

// D += A*B, m16n8k8 tf32, fp32 accumulate
__device__ __forceinline__ void mma_tf32(float* d, const uint32_t* a, const uint32_t* b) {
    asm volatile(
        "mma.sync.aligned.m16n8k8.row.col.f32.tf32.tf32.f32 "
        "{%0,%1,%2,%3},{%4,%5,%6,%7},{%8,%9},{%0,%1,%2,%3};"
        : "+f"(d[0]), "+f"(d[1]), "+f"(d[2]), "+f"(d[3])
        : "r"(a[0]), "r"(a[1]), "r"(a[2]), "r"(a[3]), "r"(b[0]), "r"(b[1]));
}

__device__ __forceinline__ void cpa(uint32_t dst, const void* src) {
    asm volatile("cp.async.cg.shared.global [%0], [%1], 16;" :: "r"(dst), "l"(src));
}
__device__ __forceinline__ void cpa_commit() { asm volatile("cp.async.commit_group;"); }
template<int N> __device__ __forceinline__ void cpa_wait() {
    asm volatile("cp.async.wait_group %0;" :: "n"(N));
}

// ---------------------------------------------------------------------------
// Prep: round x and the four weight matrices to tf32 (RN) in scratch copies.
// Makes every subsequent in-MMA truncation exact (no coherent downward bias).
// ---------------------------------------------------------------------------
__global__ void prep_kernel(const float* __restrict__ x,
                            const float* __restrict__ wq, const float* __restrict__ wk,
                            const float* __restrict__ wv, const float* __restrict__ wo)
{
    const float* src; float* dst; int n4;
    switch (blockIdx.y) {
        case 0: src = x;  dst = g_xr;    n4 = M_ROWS * DMODEL / 4; break;
        case 1: src = wq; dst = g_wr[0]; n4 = DMODEL * DMODEL / 4; break;
        case 2: src = wk; dst = g_wr[1]; n4 = DMODEL * DMODEL / 4; break;
        case 3: src = wv; dst = g_wr[2]; n4 = DMODEL * DMODEL / 4; break;
        default:src = wo; dst = g_wr[3]; n4 = DMODEL * DMODEL / 4; break;
    }
    for (int i = blockIdx.x * blockDim.x + threadIdx.x; i < n4;
         i += gridDim.x * blockDim.x) {
        float4 v = ((const float4*)src)[i];
        v.x = rna_tf32(v.x); v.y = rna_tf32(v.y);
        v.z = rna_tf32(v.z); v.w = rna_tf32(v.w);
        ((float4*)dst)[i] = v;
    }
}

// ---------------------------------------------------------------------------
// TF32 tensor-core GEMM: C[M,N] = A[M,K] * B[N,K]^T + bias[N]
// BM=BN=128, BK=32, 256 threads = 8 warps (2 M x 4 N), warp tile 64x32,
// each warp: 4x4 m16n8 fragments. 2-stage cp.async pipeline.
// Smem pad 36 floats/row -> conflict-free scalar fragment LDS (4r+k distinct).
// ---------------------------------------------------------------------------
#define GBM 128
#define GBN 128
#define GBK 32
#define GPAD 36
#define GST (GBM * GPAD)              // 4608 floats per tile
#define GSTAGE (2 * GST)              // A+B per stage (floats)
#define GEMM_SMEM (2 * GSTAGE * 4)    // 73728 bytes

template<bool GATHER_A, bool SCATTER_C>
__device__ __forceinline__ void gemm_tf32_body(
    const float* __restrict__ A, const float* __restrict__ B,
    const float* __restrict__ bias, float* __restrict__ C)
{
    extern __shared__ float sm[];
    const int tid  = threadIdx.x;
    const int lane = tid & 31;
    const int warp = tid >> 5;
    const int wm   = warp >> 2;     // 0..1
    const int wn   = warp & 3;      // 0..3
    const int row0 = blockIdx.y * GBM;
    const int col0 = blockIdx.x * GBN;

    const uint32_t smbase = (uint32_t)__cvta_generic_to_shared(sm);

    float acc[4][4][4];
#pragma unroll
    for (int mi = 0; mi < 4; mi++)
#pragma unroll
        for (int ni = 0; ni < 4; ni++)
#pragma unroll
            for (int e = 0; e < 4; e++) acc[mi][ni][e] = 0.0f;

    auto load_stage = [&](int s, int k0) {
        uint32_t asb = smbase + (uint32_t)(s * GSTAGE * 4);
        uint32_t bsb = asb + (uint32_t)(GST * 4);
#pragma unroll
        for (int i = 0; i < 4; i++) {
            int idx = i * 256 + tid;
            int r = idx >> 3, c = idx & 7;
            int k = k0 + c * 4;
            const float* sa;
            if (GATHER_A) {
                int m = row0 + r;
                sa = A + (size_t)(m >> 11) * BATCH_STRIDE
                       + (size_t)(m & (S_LEN - 1)) * HD
                       + (size_t)(k >> 6) * HEAD_STRIDE + (k & 63);
            } else {
                sa = A + (size_t)(row0 + r) * DMODEL + k;
            }
            cpa(asb + (uint32_t)((r * GPAD + c * 4) * 4), sa);
            cpa(bsb + (uint32_t)((r * GPAD + c * 4) * 4),
                B + (size_t)(col0 + r) * DMODEL + k);
        }
    };

    auto compute = [&](int s) {
        const float* As = sm + s * GSTAGE;
        const float* Bs = As + GST;
#pragma unroll
        for (int ks = 0; ks < 4; ks++) {
            const int kk = ks * 8 + (lane & 3);
            uint32_t a[4][4], b[4][2];
#pragma unroll
            for (int mi = 0; mi < 4; mi++) {
                int r = wm * 64 + mi * 16 + (lane >> 2);
                a[mi][0] = __float_as_uint(As[r * GPAD + kk]);
                a[mi][1] = __float_as_uint(As[(r + 8) * GPAD + kk]);
                a[mi][2] = __float_as_uint(As[r * GPAD + kk + 4]);
                a[mi][3] = __float_as_uint(As[(r + 8) * GPAD + kk + 4]);
            }
#pragma unroll
            for (int ni = 0; ni < 4; ni++) {
                int cN = wn * 32 + ni * 8 + (lane >> 2);
                b[ni][0] = __float_as_uint(Bs[cN * GPAD + kk]);
                b[ni][1] = __float_as_uint(Bs[cN * GPAD + kk + 4]);
            }
#pragma unroll
            for (int mi = 0; mi < 4; mi++)
#pragma unroll
                for (int ni = 0; ni < 4; ni++)
                    mma_tf32(acc[mi][ni], a[mi], b[ni]);
        }
    };

    load_stage(0, 0); cpa_commit();
#pragma unroll 1
    for (int it = 0; it < DMODEL / GBK; ++it) {
        if (it < DMODEL / GBK - 1) {
            load_stage((it + 1) & 1, (it + 1) * GBK); cpa_commit();
            cpa_wait<1>();
        } else {
            cpa_wait<0>();
        }
        __syncthreads();
        compute(it & 1);
        __syncthreads();
    }

    // Epilogue: bias (+ optional tf32 rounding) + store
#pragma unroll
    for (int mi = 0; mi < 4; mi++) {
#pragma unroll
        for (int e = 0; e < 2; e++) {
            const int m = row0 + wm * 64 + mi * 16 + (lane >> 2) + e * 8;
#pragma unroll
            for (int ni = 0; ni < 4; ni++) {
                const int n = col0 + wn * 32 + ni * 8 + 2 * (lane & 3);
                float v0 = acc[mi][ni][e * 2 + 0] + bias[n];
                float v1 = acc[mi][ni][e * 2 + 1] + bias[n + 1];
                if (SCATTER_C) {
                    v0 = rna_tf32(v0); v1 = rna_tf32(v1);
                    size_t o = (size_t)((m >> 11) * NHEADS + (n >> 6)) * HEAD_STRIDE
                             + (size_t)(m & (S_LEN - 1)) * HD + (n & 63);
                    *(float2*)(C + o) = make_float2(v0, v1);
                } else {
                    *(float2*)(C + (size_t)m * DMODEL + n) = make_float2(v0, v1);
                }
            }
        }
    }
}

__global__ __launch_bounds__(256) void qkv_gemm_kernel(
    const float* __restrict__ bq, const float* __restrict__ bk, const float* __restrict__ bv)
{
    const float* W; const float* b; float* out;
    if (blockIdx.z == 0)      { W = g_wr[0]; b = bq; out = g_q; }
    else if (blockIdx.z == 1) { W = g_wr[1]; b = bk; out = g_k; }
    else                      { W = g_wr[2]; b = bv; out = g_v; }
    gemm_tf32_body<false, true>(g_xr, W, b, out);
}

__global__ __launch_bounds__(256) void out_gemm_kernel(
    const float* __restrict__ bo, float* __restrict__ out)
{
    gemm_tf32_body<true, false>(g_ctx, g_wr[3], bo, out);
}

// ---------------------------------------------------------------------------
// TF32 flash attention, causal. CTA = 64 queries of one (b,h), 128 threads,
// 4 warps x m16 query rows. Q resident in A-fragments (pre-scaled by 1/8).
// K/V tiles (64x64) double-buffered via cp.async, pad 68 -> conflict-free
// scalar B-fragment LDS. P accum -> A-frag via intra-quad shuffles (no smem).
// ---------------------------------------------------------------------------
#define APAD 68
#define ATILE (64 * APAD)             // floats
#define ASTAGE (2 * ATILE)            // K+V per stage
#define ATTN_SMEM (2 * ASTAGE * 4)    // 69632 bytes

__global__ __launch_bounds__(128) void attn_tf32_kernel()
{
    extern __shared__ float sm[];
    const int tid  = threadIdx.x;
    const int lane = tid & 31;
    const int warp = tid >> 5;
    const int qb   = blockIdx.x;
    const int bh   = blockIdx.y;

    const size_t base = (size_t)bh * HEAD_STRIDE;
    const float* Qg = g_q + base + (size_t)qb * 64 * HD;
    const float* Kg = g_k + base;
    const float* Vg = g_v + base;
    float*       Og = g_ctx + base + (size_t)qb * 64 * HD;

    const uint32_t smbase = (uint32_t)__cvta_generic_to_shared(sm);
    const int q3 = lane & 3;
    const int r4 = lane >> 2;

    // Q fragments, resident (q already tf32-rounded; *0.125 is exact)
    uint32_t qa[8][4];
    {
        const int r0 = warp * 16 + r4;
#pragma unroll
        for (int ks = 0; ks < 8; ks++) {
            int k = ks * 8 + q3;
            qa[ks][0] = __float_as_uint(Qg[r0 * HD + k] * 0.125f);
            qa[ks][1] = __float_as_uint(Qg[(r0 + 8) * HD + k] * 0.125f);
            qa[ks][2] = __float_as_uint(Qg[r0 * HD + k + 4] * 0.125f);
            qa[ks][3] = __float_as_uint(Qg[(r0 + 8) * HD + k + 4] * 0.125f);
        }
    }

    float o[8][4];
#pragma unroll
    for (int f = 0; f < 8; f++)
#pragma unroll
        for (int e = 0; e < 4; e++) o[f][e] = 0.0f;
    float m0 = -1e30f, m1 = -1e30f, l0 = 0.0f, l1 = 0.0f;

    auto loadKV = [&](int s, int kb) {
        uint32_t kbs = smbase + (uint32_t)(s * ASTAGE * 4);
        uint32_t vbs = kbs + (uint32_t)(ATILE * 4);
        const float* Kt = Kg + (size_t)kb * 64 * HD;
        const float* Vt = Vg + (size_t)kb * 64 * HD;
#pragma unroll
        for (int i = 0; i < 8; i++) {
            int idx = i * 128 + tid;
            int r = idx >> 4, c = idx & 15;
            cpa(kbs + (uint32_t)((r * APAD + c * 4) * 4), Kt + r * HD + c * 4);
            cpa(vbs + (uint32_t)((r * APAD + c * 4) * 4), Vt + r * HD + c * 4);
        }
    };

    loadKV(0, 0); cpa_commit();

#pragma unroll 1
    for (int kb = 0; kb <= qb; ++kb) {
        if (kb < qb) {
            loadKV((kb + 1) & 1, kb + 1); cpa_commit();
            cpa_wait<1>();
        } else {
            cpa_wait<0>();
        }
        __syncthreads();
        const float* Ks = sm + (kb & 1) * ASTAGE;
        const float* Vs = Ks + ATILE;

        // S = (Q/8) K^T   (m16 x n64, 8 n-frags)
        float s4[8][4];
#pragma unroll
        for (int f = 0; f < 8; f++)
#pragma unroll
            for (int e = 0; e < 4; e++) s4[f][e] = 0.0f;
#pragma unroll
        for (int f = 0; f < 8; f++) {
            const int nrow = f * 8 + r4;
#pragma unroll
            for (int ks = 0; ks < 8; ks++) {
                uint32_t b[2];
                b[0] = __float_as_uint(Ks[nrow * APAD + ks * 8 + q3]);
                b[1] = __float_as_uint(Ks[nrow * APAD + ks * 8 + q3 + 4]);
                mma_tf32(s4[f], qa[ks], b);
            }
        }

        // Causal mask on diagonal tile
        if (kb == qb) {
            const int rg = warp * 16 + r4;
#pragma unroll
            for (int f = 0; f < 8; f++) {
                const int c0 = f * 8 + 2 * q3;
                if (c0     > rg)     s4[f][0] = -1e30f;
                if (c0 + 1 > rg)     s4[f][1] = -1e30f;
                if (c0     > rg + 8) s4[f][2] = -1e30f;
                if (c0 + 1 > rg + 8) s4[f][3] = -1e30f;
            }
        }

        // Online softmax (2 rows per thread; quad shuffles over lane%4)
        float mx0 = -1e30f, mx1 = -1e30f;
#pragma unroll
        for (int f = 0; f < 8; f++) {
            mx0 = fmaxf(mx0, fmaxf(s4[f][0], s4[f][1]));
            mx1 = fmaxf(mx1, fmaxf(s4[f][2], s4[f][3]));
        }
        mx0 = fmaxf(mx0, __shfl_xor_sync(0xffffffffu, mx0, 1));
        mx0 = fmaxf(mx0, __shfl_xor_sync(0xffffffffu, mx0, 2));
        mx1 = fmaxf(mx1, __shfl_xor_sync(0xffffffffu, mx1, 1));
        mx1 = fmaxf(mx1, __shfl_xor_sync(0xffffffffu, mx1, 2));
        const float nm0 = fmaxf(m0, mx0), nm1 = fmaxf(m1, mx1);
        const float al0 = __expf(m0 - nm0), al1 = __expf(m1 - nm1);
        float rs0 = 0.0f, rs1 = 0.0f;
#pragma unroll
        for (int f = 0; f < 8; f++) {
            s4[f][0] = rna_tf32(__expf(s4[f][0] - nm0));
            s4[f][1] = rna_tf32(__expf(s4[f][1] - nm0));
            s4[f][2] = rna_tf32(__expf(s4[f][2] - nm1));
            s4[f][3] = rna_tf32(__expf(s4[f][3] - nm1));
            rs0 += s4[f][0] + s4[f][1];
            rs1 += s4[f][2] + s4[f][3];
        }
        rs0 += __shfl_xor_sync(0xffffffffu, rs0, 1);
        rs0 += __shfl_xor_sync(0xffffffffu, rs0, 2);
        rs1 += __shfl_xor_sync(0xffffffffu, rs1, 1);
        rs1 += __shfl_xor_sync(0xffffffffu, rs1, 2);
        l0 = l0 * al0 + rs0;  l1 = l1 * al1 + rs1;
        m0 = nm0;  m1 = nm1;
#pragma unroll
        for (int f = 0; f < 8; f++) {
            o[f][0] *= al0; o[f][1] *= al0;
            o[f][2] *= al1; o[f][3] *= al1;
        }

        // O += P V  (k = kv position; P accum -> A-frag via quad shuffles)
        const int bl = lane & ~3;
        const int s0l = bl | (q3 >> 1);
        const int s2l = bl | (2 + (q3 >> 1));
#pragma unroll
        for (int s = 0; s < 8; s++) {
            float v00 = __shfl_sync(0xffffffffu, s4[s][0], s0l);
            float v01 = __shfl_sync(0xffffffffu, s4[s][1], s0l);
            float v10 = __shfl_sync(0xffffffffu, s4[s][2], s0l);
            float v11 = __shfl_sync(0xffffffffu, s4[s][3], s0l);
            float w00 = __shfl_sync(0xffffffffu, s4[s][0], s2l);
            float w01 = __shfl_sync(0xffffffffu, s4[s][1], s2l);
            float w10 = __shfl_sync(0xffffffffu, s4[s][2], s2l);
            float w11 = __shfl_sync(0xffffffffu, s4[s][3], s2l);
            uint32_t pa[4];
            pa[0] = __float_as_uint((q3 & 1) ? v01 : v00);
            pa[1] = __float_as_uint((q3 & 1) ? v11 : v10);
            pa[2] = __float_as_uint((q3 & 1) ? w01 : w00);
            pa[3] = __float_as_uint((q3 & 1) ? w11 : w10);
            const int krow = s * 8 + q3;
#pragma unroll
            for (int f = 0; f < 8; f++) {
                uint32_t b[2];
                b[0] = __float_as_uint(Vs[krow * APAD + f * 8 + r4]);
                b[1] = __float_as_uint(Vs[(krow + 4) * APAD + f * 8 + r4]);
                mma_tf32(o[f], pa, b);
            }
        }
        __syncthreads();
    }

    // Epilogue: normalize, round to tf32, store ctx [B,H,S,hd]
    const float il0 = 1.0f / l0, il1 = 1.0f / l1;
    const int r0g = warp * 16 + r4;
#pragma unroll
    for (int f = 0; f < 8; f++) {
        const int cc = f * 8 + 2 * q3;
        float2 p0 = make_float2(rna_tf32(o[f][0] * il0), rna_tf32(o[f][1] * il0));
        float2 p1 = make_float2(rna_tf32(o[f][2] * il1), rna_tf32(o[f][3] * il1));
        *(float2*)(Og + (size_t)r0g * HD + cc)       = p0;
        *(float2*)(Og + (size_t)(r0g + 8) * HD + cc) = p1;
    }
}

// ---------------------------------------------------------------------------
extern "C" void kernel_launch(void* const* d_in, const int* in_sizes, int n_in,
                              void* d_out, int out_size)
{
    (void)in_sizes; (void)n_in; (void)out_size;
    const float* x  = (const float*)d_in[0];
    const float* Wq = (const float*)d_in[1];
    const float* bq = (const float*)d_in[2];
    const float* Wk = (const float*)d_in[3];
    const float* bk = (const float*)d_in[4];
    const float* Wv = (const float*)d_in[5];
    const float* bv = (const float*)d_in[6];
    const float* Wo = (const float*)d_in[7];
    const float* bo = (const float*)d_in[8];
    float* out = (float*)d_out;

    // Host-side, idempotent, capture-safe
    cudaFuncSetAttribute(qkv_gemm_kernel, cudaFuncAttributeMaxDynamicSharedMemorySize, GEMM_SMEM);
    cudaFuncSetAttribute(out_gemm_kernel, cudaFuncAttributeMaxDynamicSharedMemorySize, GEMM_SMEM);
    cudaFuncSetAttribute(attn_tf32_kernel, cudaFuncAttributeMaxDynamicSharedMemorySize, ATTN_SMEM);

    // 0) Round x + weights to tf32 scratch copies
    prep_kernel<<<dim3(128, 5), 256>>>(x, Wq, Wk, Wv, Wo);
    // 1) QKV projections (tensor cores) -> g_q/g_k/g_v [B,H,S,hd], tf32-rounded
    qkv_gemm_kernel<<<dim3(DMODEL / GBN, M_ROWS / GBM, 3), 256, GEMM_SMEM>>>(bq, bk, bv);
    // 2) Causal flash attention (tensor cores) -> g_ctx, tf32-rounded
    attn_tf32_kernel<<<dim3(S_LEN / 64, BHTOT), 128, ATTN_SMEM>>>();
    // 3) Output projection (tensor cores) -> d_out
    out_gemm_kernel<<<dim3(DMODEL / GBN, M_ROWS / GBM), 256, GEMM_SMEM>>>(bo, out);
}

// round 9
// speedup vs baseline: 7.0110x; 1.2968x over previous
#include <cuda_runtime.h>
#include <cstdint>

// ---------------------------------------------------------------------------
// Problem constants
// ---------------------------------------------------------------------------
#define BATCH   2
#define S_LEN   2048
#define DMODEL  1024
#define NHEADS  16
#define HD      64
#define BHTOT   (BATCH * NHEADS)          // 32
#define M_ROWS  (BATCH * S_LEN)           // 4096
#define HEAD_STRIDE  (S_LEN * HD)         // 131072
#define BATCH_STRIDE (NHEADS * S_LEN * HD)

// Scratch (device globals; no allocations allowed)
__device__ float g_q  [BHTOT * S_LEN * HD];
__device__ float g_k  [BHTOT * S_LEN * HD];
__device__ float g_v  [BHTOT * S_LEN * HD];
__device__ float g_ctx[BHTOT * S_LEN * HD];
__device__ float g_xr [M_ROWS * DMODEL];          // tf32-rounded x
__device__ float g_wr [4][DMODEL * DMODEL];       // tf32-rounded Wq,Wk,Wv,Wo

// ---------------------------------------------------------------------------
// Helpers
// ---------------------------------------------------------------------------
__device__ __forceinline__ float rna_tf32(float v) {
    uint32_t o;
    asm("cvt.rna.tf32.f32 %0, %1;" : "=r"(o) : "f"(v));
    return __uint_as_float(o);
}

// D += A*B, m16n8k8 tf32, fp32 accumulate
__device__ __forceinline__ void mma_tf32(float* d, const uint32_t* a, const uint32_t* b) {
    asm volatile(
        "mma.sync.aligned.m16n8k8.row.col.f32.tf32.tf32.f32 "
        "{%0,%1,%2,%3},{%4,%5,%6,%7},{%8,%9},{%0,%1,%2,%3};"
        : "+f"(d[0]), "+f"(d[1]), "+f"(d[2]), "+f"(d[3])
        : "r"(a[0]), "r"(a[1]), "r"(a[2]), "r"(a[3]), "r"(b[0]), "r"(b[1]));
}

__device__ __forceinline__ void cpa(uint32_t dst, const void* src) {
    asm volatile("cp.async.cg.shared.global [%0], [%1], 16;" :: "r"(dst), "l"(src));
}
__device__ __forceinline__ void cpa_commit() { asm volatile("cp.async.commit_group;"); }
template<int N> __device__ __forceinline__ void cpa_wait() {
    asm volatile("cp.async.wait_group %0;" :: "n"(N));
}

// ldmatrix x4: four 8x8 b16 (= 8x4 b32) matrices; lane L supplies row addr for
// matrix L/8 (row L%8). Thread T receives element (row T/4, b32-col T%4) of
// each matrix -> exactly one tf32 m16n8k8 operand register per matrix.
__device__ __forceinline__ void ldsm4(uint32_t* d, uint32_t addr) {
    asm volatile("ldmatrix.sync.aligned.m8n8.x4.shared.b16 {%0,%1,%2,%3}, [%4];"
        : "=r"(d[0]), "=r"(d[1]), "=r"(d[2]), "=r"(d[3]) : "r"(addr));
}

// ---------------------------------------------------------------------------
// Prep: round x and the four weight matrices to tf32 (RN) in scratch copies.
// ---------------------------------------------------------------------------
__global__ void prep_kernel(const float* __restrict__ x,
                            const float* __restrict__ wq, const float* __restrict__ wk,
                            const float* __restrict__ wv, const float* __restrict__ wo)
{
    const float* src; float* dst; int n4;
    switch (blockIdx.y) {
        case 0: src = x;  dst = g_xr;    n4 = M_ROWS * DMODEL / 4; break;
        case 1: src = wq; dst = g_wr[0]; n4 = DMODEL * DMODEL / 4; break;
        case 2: src = wk; dst = g_wr[1]; n4 = DMODEL * DMODEL / 4; break;
        case 3: src = wv; dst = g_wr[2]; n4 = DMODEL * DMODEL / 4; break;
        default:src = wo; dst = g_wr[3]; n4 = DMODEL * DMODEL / 4; break;
    }
    for (int i = blockIdx.x * blockDim.x + threadIdx.x; i < n4;
         i += gridDim.x * blockDim.x) {
        float4 v = ((const float4*)src)[i];
        v.x = rna_tf32(v.x); v.y = rna_tf32(v.y);
        v.z = rna_tf32(v.z); v.w = rna_tf32(v.w);
        ((float4*)dst)[i] = v;
    }
}

// ---------------------------------------------------------------------------
// TF32 tensor-core GEMM: C[M,N] = A[M,K] * B[N,K]^T + bias[N]
// 128x128x32 tiles, 8 warps (2Mx4N), 3-stage cp.async pipeline,
// XOR-swizzled smem (128B rows, 16B-chunk ^ (row&7)) + ldmatrix fragments.
// One __syncthreads per K-iteration.
// ---------------------------------------------------------------------------
#define GBM 128
#define GBN 128
#define GBK 32
#define GSTB 16384                    // one 128x32 fp32 tile in bytes
#define GSTAGE_B (2 * GSTB)           // A+B per stage
#define NSTAGE 3
#define GEMM_SMEM (NSTAGE * GSTAGE_B) // 98304 bytes

template<bool GATHER_A, bool SCATTER_C>
__device__ __forceinline__ void gemm_tf32_body(
    const float* __restrict__ A, const float* __restrict__ B,
    const float* __restrict__ bias, float* __restrict__ C)
{
    extern __shared__ float sm[];
    const int tid  = threadIdx.x;
    const int lane = tid & 31;
    const int warp = tid >> 5;
    const int wm   = warp >> 2;     // 0..1
    const int wn   = warp & 3;      // 0..3
    const int row0 = blockIdx.y * GBM;
    const int col0 = blockIdx.x * GBN;

    const uint32_t smbase = (uint32_t)__cvta_generic_to_shared(sm);

    float acc[4][4][4];
#pragma unroll
    for (int mi = 0; mi < 4; mi++)
#pragma unroll
        for (int ni = 0; ni < 4; ni++)
#pragma unroll
            for (int e = 0; e < 4; e++) acc[mi][ni][e] = 0.0f;

    auto load_stage = [&](int s, int k0) {
        uint32_t asb = smbase + (uint32_t)(s * GSTAGE_B);
        uint32_t bsb = asb + GSTB;
#pragma unroll
        for (int i = 0; i < 4; i++) {
            int idx = i * 256 + tid;                // 0..1023 16B chunks
            int r = idx >> 3, c = idx & 7;
            uint32_t off = (uint32_t)(r * 128 + ((c ^ (r & 7)) << 4));
            int k = k0 + c * 4;
            const float* sa;
            if (GATHER_A) {
                int m = row0 + r;
                sa = A + (size_t)(m >> 11) * BATCH_STRIDE
                       + (size_t)(m & (S_LEN - 1)) * HD
                       + (size_t)(k >> 6) * HEAD_STRIDE + (k & 63);
            } else {
                sa = A + (size_t)(row0 + r) * DMODEL + k;
            }
            cpa(asb + off, sa);
            cpa(bsb + off, B + (size_t)(col0 + r) * DMODEL + k);
        }
    };

    // ldmatrix lane geometry (fixed per thread)
    const int g  = lane >> 3;
    const int rl = lane & 7;
    uint32_t arow[4]; int amx[4];
#pragma unroll
    for (int mi = 0; mi < 4; mi++) {
        int m = wm * 64 + mi * 16 + (g & 1) * 8 + rl;
        arow[mi] = (uint32_t)(m * 128);  amx[mi] = m & 7;
    }
    uint32_t brow[2]; int bmx[2];
#pragma unroll
    for (int j = 0; j < 2; j++) {
        int n = wn * 32 + j * 16 + (g >> 1) * 8 + rl;
        brow[j] = (uint32_t)(n * 128);  bmx[j] = n & 7;
    }
    const int akc = g >> 1;   // A chunk offset within k8-step
    const int bkc = g & 1;    // B chunk offset

    auto compute = [&](int s) {
        uint32_t asb = smbase + (uint32_t)(s * GSTAGE_B);
        uint32_t bsb = asb + GSTB;
#pragma unroll
        for (int ks = 0; ks < 4; ks++) {
            uint32_t a[4][4], bb[2][4];
#pragma unroll
            for (int mi = 0; mi < 4; mi++)
                ldsm4(a[mi], asb + arow[mi] + (uint32_t)((((2 * ks + akc) ^ amx[mi])) << 4));
#pragma unroll
            for (int j = 0; j < 2; j++)
                ldsm4(bb[j], bsb + brow[j] + (uint32_t)((((2 * ks + bkc) ^ bmx[j])) << 4));
#pragma unroll
            for (int mi = 0; mi < 4; mi++)
#pragma unroll
                for (int j = 0; j < 2; j++) {
                    mma_tf32(acc[mi][2 * j],     a[mi], &bb[j][0]);
                    mma_tf32(acc[mi][2 * j + 1], a[mi], &bb[j][2]);
                }
        }
    };

    load_stage(0, 0);    cpa_commit();
    load_stage(1, GBK);  cpa_commit();
#pragma unroll 1
    for (int it = 0; it < DMODEL / GBK; ++it) {
        cpa_wait<1>();
        __syncthreads();
        if (it + 2 < DMODEL / GBK) load_stage((it + 2) % NSTAGE, (it + 2) * GBK);
        cpa_commit();
        compute(it % NSTAGE);
    }

    // Epilogue: bias (+ tf32 rounding when feeding a later GEMM) + store
#pragma unroll
    for (int mi = 0; mi < 4; mi++) {
#pragma unroll
        for (int e = 0; e < 2; e++) {
            const int m = row0 + wm * 64 + mi * 16 + (lane >> 2) + e * 8;
#pragma unroll
            for (int ni = 0; ni < 4; ni++) {
                const int n = col0 + wn * 32 + ni * 8 + 2 * (lane & 3);
                float v0 = acc[mi][ni][e * 2 + 0] + bias[n];
                float v1 = acc[mi][ni][e * 2 + 1] + bias[n + 1];
                if (SCATTER_C) {
                    v0 = rna_tf32(v0); v1 = rna_tf32(v1);
                    size_t o = (size_t)((m >> 11) * NHEADS + (n >> 6)) * HEAD_STRIDE
                             + (size_t)(m & (S_LEN - 1)) * HD + (n & 63);
                    *(float2*)(C + o) = make_float2(v0, v1);
                } else {
                    *(float2*)(C + (size_t)m * DMODEL + n) = make_float2(v0, v1);
                }
            }
        }
    }
}

__global__ __launch_bounds__(256) void qkv_gemm_kernel(
    const float* __restrict__ bq, const float* __restrict__ bk, const float* __restrict__ bv)
{
    const float* W; const float* b; float* out;
    if (blockIdx.z == 0)      { W = g_wr[0]; b = bq; out = g_q; }
    else if (blockIdx.z == 1) { W = g_wr[1]; b = bk; out = g_k; }
    else                      { W = g_wr[2]; b = bv; out = g_v; }
    gemm_tf32_body<false, true>(g_xr, W, b, out);
}

__global__ __launch_bounds__(256) void out_gemm_kernel(
    const float* __restrict__ bo, float* __restrict__ out)
{
    gemm_tf32_body<true, false>(g_ctx, g_wr[3], bo, out);
}

// ---------------------------------------------------------------------------
// TF32 flash attention, causal. CTA = 64 queries of one (b,h), 128 threads,
// 4 warps x m16 query rows. Q resident in A-fragments (pre-scaled by 1/8).
// K: swizzled smem (256B rows) + ldmatrix B-fragments.
// V: pad-72 smem (72 = 8 mod 32 -> perfect bank permutation for scalar frags).
// P accum -> A-frag via intra-quad shuffles (no smem round-trip).
// Heavy CTAs (large qb) launch first: qb = 31 - blockIdx.x.
// ---------------------------------------------------------------------------
#define KTILE_F 4096                  // 64 x 64 floats
#define VPAD 72
#define VTILE_F (64 * VPAD)           // 4608 floats
#define ASTG_F (KTILE_F + VTILE_F)    // floats per stage
#define ATTN_SMEM (2 * ASTG_F * 4)    // 69632 bytes

__global__ __launch_bounds__(128) void attn_tf32_kernel()
{
    extern __shared__ float sm[];
    const int tid  = threadIdx.x;
    const int lane = tid & 31;
    const int warp = tid >> 5;
    const int qb   = (int)gridDim.x - 1 - (int)blockIdx.x;   // heavy first
    const int bh   = blockIdx.y;

    const size_t base = (size_t)bh * HEAD_STRIDE;
    const float* Qg = g_q + base + (size_t)qb * 64 * HD;
    const float* Kg = g_k + base;
    const float* Vg = g_v + base;
    float*       Og = g_ctx + base + (size_t)qb * 64 * HD;

    const uint32_t smbase = (uint32_t)__cvta_generic_to_shared(sm);
    const int q3 = lane & 3;
    const int r4 = lane >> 2;

    // Q fragments, resident (q already tf32-rounded; *0.125 is exact)
    uint32_t qa[8][4];
    {
        const int r0 = warp * 16 + r4;
#pragma unroll
        for (int ks = 0; ks < 8; ks++) {
            int k = ks * 8 + q3;
            qa[ks][0] = __float_as_uint(Qg[r0 * HD + k] * 0.125f);
            qa[ks][1] = __float_as_uint(Qg[(r0 + 8) * HD + k] * 0.125f);
            qa[ks][2] = __float_as_uint(Qg[r0 * HD + k + 4] * 0.125f);
            qa[ks][3] = __float_as_uint(Qg[(r0 + 8) * HD + k + 4] * 0.125f);
        }
    }

    float o[8][4];
#pragma unroll
    for (int f = 0; f < 8; f++)
#pragma unroll
        for (int e = 0; e < 4; e++) o[f][e] = 0.0f;
    float m0 = -1e30f, m1 = -1e30f, l0 = 0.0f, l1 = 0.0f;

    auto loadKV = [&](int s, int kb) {
        uint32_t kbs = smbase + (uint32_t)(s * ASTG_F * 4);
        uint32_t vbs = kbs + (uint32_t)(KTILE_F * 4);
        const float* Kt = Kg + (size_t)kb * 64 * HD;
        const float* Vt = Vg + (size_t)kb * 64 * HD;
#pragma unroll
        for (int i = 0; i < 8; i++) {
            int idx = i * 128 + tid;           // 1024 chunks of 16B
            int r = idx >> 4, c = idx & 15;
            cpa(kbs + (uint32_t)(r * 256 + ((c ^ (r & 7)) << 4)), Kt + r * HD + c * 4);
            cpa(vbs + (uint32_t)((r * VPAD + c * 4) * 4),         Vt + r * HD + c * 4);
        }
    };

    // ldmatrix lane geometry for K B-fragments
    const int g  = lane >> 3;
    const int rl = lane & 7;
    uint32_t crow[4]; int cmx[4];
#pragma unroll
    for (int j = 0; j < 4; j++) {
        int c = j * 16 + (g >> 1) * 8 + rl;
        crow[j] = (uint32_t)(c * 256);  cmx[j] = c & 7;
    }
    const int bkc = g & 1;

    loadKV(0, 0); cpa_commit();

#pragma unroll 1
    for (int kb = 0; kb <= qb; ++kb) {
        if (kb < qb) {
            loadKV((kb + 1) & 1, kb + 1); cpa_commit();
            cpa_wait<1>();
        } else {
            cpa_wait<0>();
        }
        __syncthreads();
        const uint32_t Ksb = smbase + (uint32_t)((kb & 1) * ASTG_F * 4);
        const float*   Vs  = sm + (kb & 1) * ASTG_F + KTILE_F;

        // S = (Q/8) K^T   (m16 x n64; K frags via ldmatrix)
        float s4[8][4];
#pragma unroll
        for (int f = 0; f < 8; f++)
#pragma unroll
            for (int e = 0; e < 4; e++) s4[f][e] = 0.0f;
#pragma unroll
        for (int ks = 0; ks < 8; ks++) {
            uint32_t kb4[4][4];
#pragma unroll
            for (int j = 0; j < 4; j++)
                ldsm4(kb4[j], Ksb + crow[j] + (uint32_t)((((2 * ks + bkc) ^ cmx[j])) << 4));
#pragma unroll
            for (int j = 0; j < 4; j++) {
                mma_tf32(s4[2 * j],     qa[ks], &kb4[j][0]);
                mma_tf32(s4[2 * j + 1], qa[ks], &kb4[j][2]);
            }
        }

        // Causal mask on diagonal tile
        if (kb == qb) {
            const int rg = warp * 16 + r4;
#pragma unroll
            for (int f = 0; f < 8; f++) {
                const int c0 = f * 8 + 2 * q3;
                if (c0     > rg)     s4[f][0] = -1e30f;
                if (c0 + 1 > rg)     s4[f][1] = -1e30f;
                if (c0     > rg + 8) s4[f][2] = -1e30f;
                if (c0 + 1 > rg + 8) s4[f][3] = -1e30f;
            }
        }

        // Online softmax (2 rows per thread; quad shuffles over lane%4)
        float mx0 = -1e30f, mx1 = -1e30f;
#pragma unroll
        for (int f = 0; f < 8; f++) {
            mx0 = fmaxf(mx0, fmaxf(s4[f][0], s4[f][1]));
            mx1 = fmaxf(mx1, fmaxf(s4[f][2], s4[f][3]));
        }
        mx0 = fmaxf(mx0, __shfl_xor_sync(0xffffffffu, mx0, 1));
        mx0 = fmaxf(mx0, __shfl_xor_sync(0xffffffffu, mx0, 2));
        mx1 = fmaxf(mx1, __shfl_xor_sync(0xffffffffu, mx1, 1));
        mx1 = fmaxf(mx1, __shfl_xor_sync(0xffffffffu, mx1, 2));
        const float nm0 = fmaxf(m0, mx0), nm1 = fmaxf(m1, mx1);
        const float al0 = __expf(m0 - nm0), al1 = __expf(m1 - nm1);
        float rs0 = 0.0f, rs1 = 0.0f;
#pragma unroll
        for (int f = 0; f < 8; f++) {
            s4[f][0] = rna_tf32(__expf(s4[f][0] - nm0));
            s4[f][1] = rna_tf32(__expf(s4[f][1] - nm0));
            s4[f][2] = rna_tf32(__expf(s4[f][2] - nm1));
            s4[f][3] = rna_tf32(__expf(s4[f][3] - nm1));
            rs0 += s4[f][0] + s4[f][1];
            rs1 += s4[f][2] + s4[f][3];
        }
        rs0 += __shfl_xor_sync(0xffffffffu, rs0, 1);
        rs0 += __shfl_xor_sync(0xffffffffu, rs0, 2);
        rs1 += __shfl_xor_sync(0xffffffffu, rs1, 1);
        rs1 += __shfl_xor_sync(0xffffffffu, rs1, 2);
        l0 = l0 * al0 + rs0;  l1 = l1 * al1 + rs1;
        m0 = nm0;  m1 = nm1;
#pragma unroll
        for (int f = 0; f < 8; f++) {
            o[f][0] *= al0; o[f][1] *= al0;
            o[f][2] *= al1; o[f][3] *= al1;
        }

        // O += P V  (P accum -> A-frag via quad shuffles; V scalar, pad-72)
        const int bl  = lane & ~3;
        const int s0l = bl | (q3 >> 1);
        const int s2l = bl | (2 + (q3 >> 1));
#pragma unroll
        for (int s = 0; s < 8; s++) {
            float v00 = __shfl_sync(0xffffffffu, s4[s][0], s0l);
            float v01 = __shfl_sync(0xffffffffu, s4[s][1], s0l);
            float v10 = __shfl_sync(0xffffffffu, s4[s][2], s0l);
            float v11 = __shfl_sync(0xffffffffu, s4[s][3], s0l);
            float w00 = __shfl_sync(0xffffffffu, s4[s][0], s2l);
            float w01 = __shfl_sync(0xffffffffu, s4[s][1], s2l);
            float w10 = __shfl_sync(0xffffffffu, s4[s][2], s2l);
            float w11 = __shfl_sync(0xffffffffu, s4[s][3], s2l);
            uint32_t pa[4];
            pa[0] = __float_as_uint((q3 & 1) ? v01 : v00);
            pa[1] = __float_as_uint((q3 & 1) ? v11 : v10);
            pa[2] = __float_as_uint((q3 & 1) ? w01 : w00);
            pa[3] = __float_as_uint((q3 & 1) ? w11 : w10);
            const int krow = s * 8 + q3;
#pragma unroll
            for (int f = 0; f < 8; f++) {
                uint32_t b[2];
                b[0] = __float_as_uint(Vs[krow * VPAD + f * 8 + r4]);
                b[1] = __float_as_uint(Vs[(krow + 4) * VPAD + f * 8 + r4]);
                mma_tf32(o[f], pa, b);
            }
        }
        __syncthreads();
    }

    // Epilogue: normalize, round to tf32 (feeds out-proj), store ctx [B,H,S,hd]
    const float il0 = 1.0f / l0, il1 = 1.0f / l1;
    const int r0g = warp * 16 + r4;
#pragma unroll
    for (int f = 0; f < 8; f++) {
        const int cc = f * 8 + 2 * q3;
        float2 p0 = make_float2(rna_tf32(o[f][0] * il0), rna_tf32(o[f][1] * il0));
        float2 p1 = make_float2(rna_tf32(o[f][2] * il1), rna_tf32(o[f][3] * il1));
        *(float2*)(Og + (size_t)r0g * HD + cc)       = p0;
        *(float2*)(Og + (size_t)(r0g + 8) * HD + cc) = p1;
    }
}

// ---------------------------------------------------------------------------
extern "C" void kernel_launch(void* const* d_in, const int* in_sizes, int n_in,
                              void* d_out, int out_size)
{
    (void)in_sizes; (void)n_in; (void)out_size;
    const float* x  = (const float*)d_in[0];
    const float* Wq = (const float*)d_in[1];
    const float* bq = (const float*)d_in[2];
    const float* Wk = (const float*)d_in[3];
    const float* bk = (const float*)d_in[4];
    const float* Wv = (const float*)d_in[5];
    const float* bv = (const float*)d_in[6];
    const float* Wo = (const float*)d_in[7];
    const float* bo = (const float*)d_in[8];
    float* out = (float*)d_out;

    // Host-side, idempotent, capture-safe
    cudaFuncSetAttribute(qkv_gemm_kernel, cudaFuncAttributeMaxDynamicSharedMemorySize, GEMM_SMEM);
    cudaFuncSetAttribute(out_gemm_kernel, cudaFuncAttributeMaxDynamicSharedMemorySize, GEMM_SMEM);
    cudaFuncSetAttribute(attn_tf32_kernel, cudaFuncAttributeMaxDynamicSharedMemorySize, ATTN_SMEM);

    // 0) Round x + weights to tf32 scratch copies
    prep_kernel<<<dim3(128, 5), 256>>>(x, Wq, Wk, Wv, Wo);
    // 1) QKV projections -> g_q/g_k/g_v [B,H,S,hd], tf32-rounded
    qkv_gemm_kernel<<<dim3(DMODEL / GBN, M_ROWS / GBM, 3), 256, GEMM_SMEM>>>(bq, bk, bv);
    // 2) Causal flash attention -> g_ctx, tf32-rounded
    attn_tf32_kernel<<<dim3(S_LEN / 64, BHTOT), 128, ATTN_SMEM>>>();
    // 3) Output projection -> d_out
    out_gemm_kernel<<<dim3(DMODEL / GBN, M_ROWS / GBM), 256, GEMM_SMEM>>>(bo, out);
}

// round 12
// speedup vs baseline: 7.0256x; 1.0021x over previous
#include <cuda_runtime.h>
#include <cstdint>

// ---------------------------------------------------------------------------
// Problem constants
// ---------------------------------------------------------------------------
#define BATCH   2
#define S_LEN   2048
#define DMODEL  1024
#define NHEADS  16
#define HD      64
#define BHTOT   (BATCH * NHEADS)          // 32
#define M_ROWS  (BATCH * S_LEN)           // 4096
#define HEAD_STRIDE  (S_LEN * HD)         // 131072
#define BATCH_STRIDE (NHEADS * S_LEN * HD)

// Scratch (device globals; no allocations allowed)
__device__ float g_q  [BHTOT * S_LEN * HD];
__device__ float g_k  [BHTOT * S_LEN * HD];
__device__ float g_v  [BHTOT * S_LEN * HD];
__device__ float g_ctx[BHTOT * S_LEN * HD];
__device__ float g_xr [M_ROWS * DMODEL];          // tf32-rounded x
__device__ float g_wr [4][DMODEL * DMODEL];       // tf32-rounded Wq,Wk,Wv,Wo

// ---------------------------------------------------------------------------
// Helpers
// ---------------------------------------------------------------------------
__device__ __forceinline__ float rna_tf32(float v) {
    uint32_t o;
    asm("cvt.rna.tf32.f32 %0, %1;" : "=r"(o) : "f"(v));
    return __uint_as_float(o);
}

// D += A*B, m16n8k8 tf32, fp32 accumulate
__device__ __forceinline__ void mma_tf32(float* d, const uint32_t* a, const uint32_t* b) {
    asm volatile(
        "mma.sync.aligned.m16n8k8.row.col.f32.tf32.tf32.f32 "
        "{%0,%1,%2,%3},{%4,%5,%6,%7},{%8,%9},{%0,%1,%2,%3};"
        : "+f"(d[0]), "+f"(d[1]), "+f"(d[2]), "+f"(d[3])
        : "r"(a[0]), "r"(a[1]), "r"(a[2]), "r"(a[3]), "r"(b[0]), "r"(b[1]));
}

__device__ __forceinline__ void cpa(uint32_t dst, const void* src) {
    asm volatile("cp.async.cg.shared.global [%0], [%1], 16;" :: "r"(dst), "l"(src));
}
__device__ __forceinline__ void cpa_commit() { asm volatile("cp.async.commit_group;"); }
template<int N> __device__ __forceinline__ void cpa_wait() {
    asm volatile("cp.async.wait_group %0;" :: "n"(N));
}

// ldmatrix x4: four 8x8 b16 (= 8x4 b32) matrices; lane L supplies row addr for
// matrix L/8 (row L%8). Thread T receives element (row T/4, b32-col T%4) of
// each matrix -> exactly one tf32 m16n8k8 operand register per matrix.
__device__ __forceinline__ void ldsm4(uint32_t* d, uint32_t addr) {
    asm volatile("ldmatrix.sync.aligned.m8n8.x4.shared.b16 {%0,%1,%2,%3}, [%4];"
        : "=r"(d[0]), "=r"(d[1]), "=r"(d[2]), "=r"(d[3]) : "r"(addr));
}

// ---------------------------------------------------------------------------
// Prep: round x and the four weight matrices to tf32 (RN) in scratch copies.
// ---------------------------------------------------------------------------
__global__ void prep_kernel(const float* __restrict__ x,
                            const float* __restrict__ wq, const float* __restrict__ wk,
                            const float* __restrict__ wv, const float* __restrict__ wo)
{
    const float* src; float* dst; int n4;
    switch (blockIdx.y) {
        case 0: src = x;  dst = g_xr;    n4 = M_ROWS * DMODEL / 4; break;
        case 1: src = wq; dst = g_wr[0]; n4 = DMODEL * DMODEL / 4; break;
        case 2: src = wk; dst = g_wr[1]; n4 = DMODEL * DMODEL / 4; break;
        case 3: src = wv; dst = g_wr[2]; n4 = DMODEL * DMODEL / 4; break;
        default:src = wo; dst = g_wr[3]; n4 = DMODEL * DMODEL / 4; break;
    }
    for (int i = blockIdx.x * blockDim.x + threadIdx.x; i < n4;
         i += gridDim.x * blockDim.x) {
        float4 v = ((const float4*)src)[i];
        v.x = rna_tf32(v.x); v.y = rna_tf32(v.y);
        v.z = rna_tf32(v.z); v.w = rna_tf32(v.w);
        ((float4*)dst)[i] = v;
    }
}

// ---------------------------------------------------------------------------
// TF32 tensor-core GEMM: C[M,N] = A[M,K] * B[N,K]^T + bias[N]
// 128x128x32 tiles, 8 warps (2Mx4N), 3-stage cp.async pipeline,
// XOR-swizzled smem (128B rows, 16B-chunk ^ (row&7)) + ldmatrix fragments.
// One __syncthreads per K-iteration. 2 CTAs/SM (regs capped at 128) so a
// co-resident CTA fills the ~47% of tensor-issue slots one CTA leaves idle.
// ---------------------------------------------------------------------------
#define GBM 128
#define GBN 128
#define GBK 32
#define GSTB 16384                    // one 128x32 fp32 tile in bytes
#define GSTAGE_B (2 * GSTB)           // A+B per stage
#define NSTAGE 3
#define GEMM_SMEM (NSTAGE * GSTAGE_B) // 98304 bytes

template<bool GATHER_A, bool SCATTER_C>
__device__ __forceinline__ void gemm_tf32_body(
    const float* __restrict__ A, const float* __restrict__ B,
    const float* __restrict__ bias, float* __restrict__ C)
{
    extern __shared__ float sm[];
    const int tid  = threadIdx.x;
    const int lane = tid & 31;
    const int warp = tid >> 5;
    const int wm   = warp >> 2;     // 0..1
    const int wn   = warp & 3;      // 0..3
    const int row0 = blockIdx.y * GBM;
    const int col0 = blockIdx.x * GBN;

    const uint32_t smbase = (uint32_t)__cvta_generic_to_shared(sm);

    float acc[4][4][4];
#pragma unroll
    for (int mi = 0; mi < 4; mi++)
#pragma unroll
        for (int ni = 0; ni < 4; ni++)
#pragma unroll
            for (int e = 0; e < 4; e++) acc[mi][ni][e] = 0.0f;

    auto load_stage = [&](int s, int k0) {
        uint32_t asb = smbase + (uint32_t)(s * GSTAGE_B);
        uint32_t bsb = asb + GSTB;
#pragma unroll
        for (int i = 0; i < 4; i++) {
            int idx = i * 256 + tid;                // 0..1023 16B chunks
            int r = idx >> 3, c = idx & 7;
            uint32_t off = (uint32_t)(r * 128 + ((c ^ (r & 7)) << 4));
            int k = k0 + c * 4;
            const float* sa;
            if (GATHER_A) {
                int m = row0 + r;
                sa = A + (size_t)(m >> 11) * BATCH_STRIDE
                       + (size_t)(m & (S_LEN - 1)) * HD
                       + (size_t)(k >> 6) * HEAD_STRIDE + (k & 63);
            } else {
                sa = A + (size_t)(row0 + r) * DMODEL + k;
            }
            cpa(asb + off, sa);
            cpa(bsb + off, B + (size_t)(col0 + r) * DMODEL + k);
        }
    };

    // ldmatrix lane geometry (fixed per thread)
    const int g  = lane >> 3;
    const int rl = lane & 7;
    uint32_t arow[4]; int amx[4];
#pragma unroll
    for (int mi = 0; mi < 4; mi++) {
        int m = wm * 64 + mi * 16 + (g & 1) * 8 + rl;
        arow[mi] = (uint32_t)(m * 128);  amx[mi] = m & 7;
    }
    uint32_t brow[2]; int bmx[2];
#pragma unroll
    for (int j = 0; j < 2; j++) {
        int n = wn * 32 + j * 16 + (g >> 1) * 8 + rl;
        brow[j] = (uint32_t)(n * 128);  bmx[j] = n & 7;
    }
    const int akc = g >> 1;   // A chunk offset within k8-step
    const int bkc = g & 1;    // B chunk offset

    auto compute = [&](int s) {
        uint32_t asb = smbase + (uint32_t)(s * GSTAGE_B);
        uint32_t bsb = asb + GSTB;
#pragma unroll
        for (int ks = 0; ks < 4; ks++) {
            uint32_t a[4][4], bb[2][4];
#pragma unroll
            for (int mi = 0; mi < 4; mi++)
                ldsm4(a[mi], asb + arow[mi] + (uint32_t)((((2 * ks + akc) ^ amx[mi])) << 4));
#pragma unroll
            for (int j = 0; j < 2; j++)
                ldsm4(bb[j], bsb + brow[j] + (uint32_t)((((2 * ks + bkc) ^ bmx[j])) << 4));
#pragma unroll
            for (int mi = 0; mi < 4; mi++)
#pragma unroll
                for (int j = 0; j < 2; j++) {
                    mma_tf32(acc[mi][2 * j],     a[mi], &bb[j][0]);
                    mma_tf32(acc[mi][2 * j + 1], a[mi], &bb[j][2]);
                }
        }
    };

    load_stage(0, 0);    cpa_commit();
    load_stage(1, GBK);  cpa_commit();
#pragma unroll 1
    for (int it = 0; it < DMODEL / GBK; ++it) {
        cpa_wait<1>();
        __syncthreads();
        if (it + 2 < DMODEL / GBK) load_stage((it + 2) % NSTAGE, (it + 2) * GBK);
        cpa_commit();
        compute(it % NSTAGE);
    }

    // Epilogue: bias (+ tf32 rounding when feeding a later GEMM) + store
#pragma unroll
    for (int mi = 0; mi < 4; mi++) {
#pragma unroll
        for (int e = 0; e < 2; e++) {
            const int m = row0 + wm * 64 + mi * 16 + (lane >> 2) + e * 8;
#pragma unroll
            for (int ni = 0; ni < 4; ni++) {
                const int n = col0 + wn * 32 + ni * 8 + 2 * (lane & 3);
                float v0 = acc[mi][ni][e * 2 + 0] + bias[n];
                float v1 = acc[mi][ni][e * 2 + 1] + bias[n + 1];
                if (SCATTER_C) {
                    v0 = rna_tf32(v0); v1 = rna_tf32(v1);
                    size_t o = (size_t)((m >> 11) * NHEADS + (n >> 6)) * HEAD_STRIDE
                             + (size_t)(m & (S_LEN - 1)) * HD + (n & 63);
                    *(float2*)(C + o) = make_float2(v0, v1);
                } else {
                    *(float2*)(C + (size_t)m * DMODEL + n) = make_float2(v0, v1);
                }
            }
        }
    }
}

__global__ __launch_bounds__(256, 2) void qkv_gemm_kernel(
    const float* __restrict__ bq, const float* __restrict__ bk, const float* __restrict__ bv)
{
    const float* W; const float* b; float* out;
    if (blockIdx.z == 0)      { W = g_wr[0]; b = bq; out = g_q; }
    else if (blockIdx.z == 1) { W = g_wr[1]; b = bk; out = g_k; }
    else                      { W = g_wr[2]; b = bv; out = g_v; }
    gemm_tf32_body<false, true>(g_xr, W, b, out);
}

__global__ __launch_bounds__(256, 2) void out_gemm_kernel(
    const float* __restrict__ bo, float* __restrict__ out)
{
    gemm_tf32_body<true, false>(g_ctx, g_wr[3], bo, out);
}

// ---------------------------------------------------------------------------
// TF32 flash attention, causal. CTA = 64 queries of one (b,h), 128 threads,
// 4 warps x m16 query rows. Q resident in A-fragments (pre-scaled by 1/8).
// K: swizzled smem (256B rows) + ldmatrix B-fragments.
// V: pad-72 smem (72 = 8 mod 32 -> perfect bank permutation for scalar frags).
// P accum -> A-frag via intra-quad shuffles (no smem round-trip).
// Heavy CTAs (large qb) launch first. 3 CTAs/SM guaranteed via launch bounds.
// ---------------------------------------------------------------------------
#define KTILE_F 4096                  // 64 x 64 floats
#define VPAD 72
#define VTILE_F (64 * VPAD)           // 4608 floats
#define ASTG_F (KTILE_F + VTILE_F)    // floats per stage
#define ATTN_SMEM (2 * ASTG_F * 4)    // 69632 bytes

__global__ __launch_bounds__(128, 3) void attn_tf32_kernel()
{
    extern __shared__ float sm[];
    const int tid  = threadIdx.x;
    const int lane = tid & 31;
    const int warp = tid >> 5;
    const int qb   = (int)gridDim.x - 1 - (int)blockIdx.x;   // heavy first
    const int bh   = blockIdx.y;

    const size_t base = (size_t)bh * HEAD_STRIDE;
    const float* Qg = g_q + base + (size_t)qb * 64 * HD;
    const float* Kg = g_k + base;
    const float* Vg = g_v + base;
    float*       Og = g_ctx + base + (size_t)qb * 64 * HD;

    const uint32_t smbase = (uint32_t)__cvta_generic_to_shared(sm);
    const int q3 = lane & 3;
    const int r4 = lane >> 2;

    // Q fragments, resident (q already tf32-rounded; *0.125 is exact)
    uint32_t qa[8][4];
    {
        const int r0 = warp * 16 + r4;
#pragma unroll
        for (int ks = 0; ks < 8; ks++) {
            int k = ks * 8 + q3;
            qa[ks][0] = __float_as_uint(Qg[r0 * HD + k] * 0.125f);
            qa[ks][1] = __float_as_uint(Qg[(r0 + 8) * HD + k] * 0.125f);
            qa[ks][2] = __float_as_uint(Qg[r0 * HD + k + 4] * 0.125f);
            qa[ks][3] = __float_as_uint(Qg[(r0 + 8) * HD + k + 4] * 0.125f);
        }
    }

    float o[8][4];
#pragma unroll
    for (int f = 0; f < 8; f++)
#pragma unroll
        for (int e = 0; e < 4; e++) o[f][e] = 0.0f;
    float m0 = -1e30f, m1 = -1e30f, l0 = 0.0f, l1 = 0.0f;

    auto loadKV = [&](int s, int kb) {
        uint32_t kbs = smbase + (uint32_t)(s * ASTG_F * 4);
        uint32_t vbs = kbs + (uint32_t)(KTILE_F * 4);
        const float* Kt = Kg + (size_t)kb * 64 * HD;
        const float* Vt = Vg + (size_t)kb * 64 * HD;
#pragma unroll
        for (int i = 0; i < 8; i++) {
            int idx = i * 128 + tid;           // 1024 chunks of 16B
            int r = idx >> 4, c = idx & 15;
            cpa(kbs + (uint32_t)(r * 256 + ((c ^ (r & 7)) << 4)), Kt + r * HD + c * 4);
            cpa(vbs + (uint32_t)((r * VPAD + c * 4) * 4),         Vt + r * HD + c * 4);
        }
    };

    // ldmatrix lane geometry for K B-fragments
    const int g  = lane >> 3;
    const int rl = lane & 7;
    uint32_t crow[4]; int cmx[4];
#pragma unroll
    for (int j = 0; j < 4; j++) {
        int c = j * 16 + (g >> 1) * 8 + rl;
        crow[j] = (uint32_t)(c * 256);  cmx[j] = c & 7;
    }
    const int bkc = g & 1;

    loadKV(0, 0); cpa_commit();

#pragma unroll 1
    for (int kb = 0; kb <= qb; ++kb) {
        if (kb < qb) {
            loadKV((kb + 1) & 1, kb + 1); cpa_commit();
            cpa_wait<1>();
        } else {
            cpa_wait<0>();
        }
        __syncthreads();
        const uint32_t Ksb = smbase + (uint32_t)((kb & 1) * ASTG_F * 4);
        const float*   Vs  = sm + (kb & 1) * ASTG_F + KTILE_F;

        // S = (Q/8) K^T   (m16 x n64; K frags via ldmatrix)
        float s4[8][4];
#pragma unroll
        for (int f = 0; f < 8; f++)
#pragma unroll
            for (int e = 0; e < 4; e++) s4[f][e] = 0.0f;
#pragma unroll
        for (int ks = 0; ks < 8; ks++) {
            uint32_t kb4[4][4];
#pragma unroll
            for (int j = 0; j < 4; j++)
                ldsm4(kb4[j], Ksb + crow[j] + (uint32_t)((((2 * ks + bkc) ^ cmx[j])) << 4));
#pragma unroll
            for (int j = 0; j < 4; j++) {
                mma_tf32(s4[2 * j],     qa[ks], &kb4[j][0]);
                mma_tf32(s4[2 * j + 1], qa[ks], &kb4[j][2]);
            }
        }

        // Causal mask on diagonal tile
        if (kb == qb) {
            const int rg = warp * 16 + r4;
#pragma unroll
            for (int f = 0; f < 8; f++) {
                const int c0 = f * 8 + 2 * q3;
                if (c0     > rg)     s4[f][0] = -1e30f;
                if (c0 + 1 > rg)     s4[f][1] = -1e30f;
                if (c0     > rg + 8) s4[f][2] = -1e30f;
                if (c0 + 1 > rg + 8) s4[f][3] = -1e30f;
            }
        }

        // Online softmax (2 rows per thread; quad shuffles over lane%4)
        float mx0 = -1e30f, mx1 = -1e30f;
#pragma unroll
        for (int f = 0; f < 8; f++) {
            mx0 = fmaxf(mx0, fmaxf(s4[f][0], s4[f][1]));
            mx1 = fmaxf(mx1, fmaxf(s4[f][2], s4[f][3]));
        }
        mx0 = fmaxf(mx0, __shfl_xor_sync(0xffffffffu, mx0, 1));
        mx0 = fmaxf(mx0, __shfl_xor_sync(0xffffffffu, mx0, 2));
        mx1 = fmaxf(mx1, __shfl_xor_sync(0xffffffffu, mx1, 1));
        mx1 = fmaxf(mx1, __shfl_xor_sync(0xffffffffu, mx1, 2));
        const float nm0 = fmaxf(m0, mx0), nm1 = fmaxf(m1, mx1);
        const float al0 = __expf(m0 - nm0), al1 = __expf(m1 - nm1);
        float rs0 = 0.0f, rs1 = 0.0f;
#pragma unroll
        for (int f = 0; f < 8; f++) {
            s4[f][0] = rna_tf32(__expf(s4[f][0] - nm0));
            s4[f][1] = rna_tf32(__expf(s4[f][1] - nm0));
            s4[f][2] = rna_tf32(__expf(s4[f][2] - nm1));
            s4[f][3] = rna_tf32(__expf(s4[f][3] - nm1));
            rs0 += s4[f][0] + s4[f][1];
            rs1 += s4[f][2] + s4[f][3];
        }
        rs0 += __shfl_xor_sync(0xffffffffu, rs0, 1);
        rs0 += __shfl_xor_sync(0xffffffffu, rs0, 2);
        rs1 += __shfl_xor_sync(0xffffffffu, rs1, 1);
        rs1 += __shfl_xor_sync(0xffffffffu, rs1, 2);
        l0 = l0 * al0 + rs0;  l1 = l1 * al1 + rs1;
        m0 = nm0;  m1 = nm1;
#pragma unroll
        for (int f = 0; f < 8; f++) {
            o[f][0] *= al0; o[f][1] *= al0;
            o[f][2] *= al1; o[f][3] *= al1;
        }

        // O += P V  (P accum -> A-frag via quad shuffles; V scalar, pad-72)
        const int bl  = lane & ~3;
        const int s0l = bl | (q3 >> 1);
        const int s2l = bl | (2 + (q3 >> 1));
#pragma unroll
        for (int s = 0; s < 8; s++) {
            float v00 = __shfl_sync(0xffffffffu, s4[s][0], s0l);
            float v01 = __shfl_sync(0xffffffffu, s4[s][1], s0l);
            float v10 = __shfl_sync(0xffffffffu, s4[s][2], s0l);
            float v11 = __shfl_sync(0xffffffffu, s4[s][3], s0l);
            float w00 = __shfl_sync(0xffffffffu, s4[s][0], s2l);
            float w01 = __shfl_sync(0xffffffffu, s4[s][1], s2l);
            float w10 = __shfl_sync(0xffffffffu, s4[s][2], s2l);
            float w11 = __shfl_sync(0xffffffffu, s4[s][3], s2l);
            uint32_t pa[4];
            pa[0] = __float_as_uint((q3 & 1) ? v01 : v00);
            pa[1] = __float_as_uint((q3 & 1) ? v11 : v10);
            pa[2] = __float_as_uint((q3 & 1) ? w01 : w00);
            pa[3] = __float_as_uint((q3 & 1) ? w11 : w10);
            const int krow = s * 8 + q3;
#pragma unroll
            for (int f = 0; f < 8; f++) {
                uint32_t b[2];
                b[0] = __float_as_uint(Vs[krow * VPAD + f * 8 + r4]);
                b[1] = __float_as_uint(Vs[(krow + 4) * VPAD + f * 8 + r4]);
                mma_tf32(o[f], pa, b);
            }
        }
        __syncthreads();
    }

    // Epilogue: normalize, round to tf32 (feeds out-proj), store ctx [B,H,S,hd]
    const float il0 = 1.0f / l0, il1 = 1.0f / l1;
    const int r0g = warp * 16 + r4;
#pragma unroll
    for (int f = 0; f < 8; f++) {
        const int cc = f * 8 + 2 * q3;
        float2 p0 = make_float2(rna_tf32(o[f][0] * il0), rna_tf32(o[f][1] * il0));
        float2 p1 = make_float2(rna_tf32(o[f][2] * il1), rna_tf32(o[f][3] * il1));
        *(float2*)(Og + (size_t)r0g * HD + cc)       = p0;
        *(float2*)(Og + (size_t)(r0g + 8) * HD + cc) = p1;
    }
}

// ---------------------------------------------------------------------------
extern "C" void kernel_launch(void* const* d_in, const int* in_sizes, int n_in,
                              void* d_out, int out_size)
{
    (void)in_sizes; (void)n_in; (void)out_size;
    const float* x  = (const float*)d_in[0];
    const float* Wq = (const float*)d_in[1];
    const float* bq = (const float*)d_in[2];
    const float* Wk = (const float*)d_in[3];
    const float* bk = (const float*)d_in[4];
    const float* Wv = (const float*)d_in[5];
    const float* bv = (const float*)d_in[6];
    const float* Wo = (const float*)d_in[7];
    const float* bo = (const float*)d_in[8];
    float* out = (float*)d_out;

    // Host-side, idempotent, capture-safe
    cudaFuncSetAttribute(qkv_gemm_kernel, cudaFuncAttributeMaxDynamicSharedMemorySize, GEMM_SMEM);
    cudaFuncSetAttribute(out_gemm_kernel, cudaFuncAttributeMaxDynamicSharedMemorySize, GEMM_SMEM);
    cudaFuncSetAttribute(attn_tf32_kernel, cudaFuncAttributeMaxDynamicSharedMemorySize, ATTN_SMEM);

    // 0) Round x + weights to tf32 scratch copies
    prep_kernel<<<dim3(128, 5), 256>>>(x, Wq, Wk, Wv, Wo);
    // 1) QKV projections -> g_q/g_k/g_v [B,H,S,hd], tf32-rounded
    qkv_gemm_kernel<<<dim3(DMODEL / GBN, M_ROWS / GBM, 3), 256, GEMM_SMEM>>>(bq, bk, bv);
    // 2) Causal flash attention -> g_ctx, tf32-rounded
    attn_tf32_kernel<<<dim3(S_LEN / 64, BHTOT), 128, ATTN_SMEM>>>();
    // 3) Output projection -> d_out
    out_gemm_kernel<<<dim3(DMODEL / GBN, M_ROWS / GBM), 256, GEMM_SMEM>>>(bo, out);
}

// round 16
// speedup vs baseline: 12.9522x; 1.8436x over previous
#include <cuda_runtime.h>
#include <cuda_fp16.h>
#include <cstdint>

// ---------------------------------------------------------------------------
// Problem constants
// ---------------------------------------------------------------------------
#define BATCH   2
#define S_LEN   2048
#define DMODEL  1024
#define NHEADS  16
#define HD      64
#define BHTOT   (BATCH * NHEADS)          // 32
#define M_ROWS  (BATCH * S_LEN)           // 4096
#define HEAD_STRIDE  (S_LEN * HD)         // 131072
#define BATCH_STRIDE (NHEADS * S_LEN * HD)

// Scratch (device globals; no allocations allowed) — all fp16
__device__ __align__(256) __half g_q  [BHTOT * S_LEN * HD];
__device__ __align__(256) __half g_k  [BHTOT * S_LEN * HD];
__device__ __align__(256) __half g_v  [BHTOT * S_LEN * HD];
__device__ __align__(256) __half g_ctx[BHTOT * S_LEN * HD];
__device__ __align__(256) __half g_xr [M_ROWS * DMODEL];      // fp16-rounded x
__device__ __align__(256) __half g_wr [4][DMODEL * DMODEL];   // fp16 Wq,Wk,Wv,Wo

// ---------------------------------------------------------------------------
// Helpers
// ---------------------------------------------------------------------------
// D += A*B, m16n8k16 fp16 inputs, fp32 accumulate
__device__ __forceinline__ void mma_f16(float* d, const uint32_t* a, const uint32_t* b) {
    asm volatile(
        "mma.sync.aligned.m16n8k16.row.col.f32.f16.f16.f32 "
        "{%0,%1,%2,%3},{%4,%5,%6,%7},{%8,%9},{%0,%1,%2,%3};"
        : "+f"(d[0]), "+f"(d[1]), "+f"(d[2]), "+f"(d[3])
        : "r"(a[0]), "r"(a[1]), "r"(a[2]), "r"(a[3]), "r"(b[0]), "r"(b[1]));
}

__device__ __forceinline__ void cpa(uint32_t dst, const void* src) {
    asm volatile("cp.async.cg.shared.global [%0], [%1], 16;" :: "r"(dst), "l"(src));
}
__device__ __forceinline__ void cpa_commit() { asm volatile("cp.async.commit_group;"); }
template<int N> __device__ __forceinline__ void cpa_wait() {
    asm volatile("cp.async.wait_group %0;" :: "n"(N));
}

__device__ __forceinline__ void ldsm4(uint32_t* d, uint32_t addr) {
    asm volatile("ldmatrix.sync.aligned.m8n8.x4.shared.b16 {%0,%1,%2,%3}, [%4];"
        : "=r"(d[0]), "=r"(d[1]), "=r"(d[2]), "=r"(d[3]) : "r"(addr));
}
__device__ __forceinline__ void ldsm4t(uint32_t* d, uint32_t addr) {
    asm volatile("ldmatrix.sync.aligned.m8n8.x4.trans.shared.b16 {%0,%1,%2,%3}, [%4];"
        : "=r"(d[0]), "=r"(d[1]), "=r"(d[2]), "=r"(d[3]) : "r"(addr));
}

__device__ __forceinline__ uint32_t h2u(__half2 h) { return *(uint32_t*)&h; }

// ---------------------------------------------------------------------------
// Prep: round x and the four weight matrices to fp16 scratch copies.
// ---------------------------------------------------------------------------
__global__ void prep_kernel(const float* __restrict__ x,
                            const float* __restrict__ wq, const float* __restrict__ wk,
                            const float* __restrict__ wv, const float* __restrict__ wo)
{
    const float* src; __half* dst; int n4;
    switch (blockIdx.y) {
        case 0: src = x;  dst = g_xr;    n4 = M_ROWS * DMODEL / 4; break;
        case 1: src = wq; dst = g_wr[0]; n4 = DMODEL * DMODEL / 4; break;
        case 2: src = wk; dst = g_wr[1]; n4 = DMODEL * DMODEL / 4; break;
        case 3: src = wv; dst = g_wr[2]; n4 = DMODEL * DMODEL / 4; break;
        default:src = wo; dst = g_wr[3]; n4 = DMODEL * DMODEL / 4; break;
    }
    for (int i = blockIdx.x * blockDim.x + threadIdx.x; i < n4;
         i += gridDim.x * blockDim.x) {
        float4 v = ((const float4*)src)[i];
        ((__half2*)dst)[2 * i]     = __float22half2_rn(make_float2(v.x, v.y));
        ((__half2*)dst)[2 * i + 1] = __float22half2_rn(make_float2(v.z, v.w));
    }
}

// ---------------------------------------------------------------------------
// FP16 tensor-core GEMM: C[M,N] = A[M,K] * B[N,K]^T + bias[N]
// 128x128x64 tiles (64 halves = 128B rows), 8 warps (2Mx4N), 3-stage cp.async,
// XOR-swizzled smem + ldmatrix. Same byte layout as the tf32 version but
// 2x K per stage and k16 MMAs -> half the iterations, half the MMA count.
// ---------------------------------------------------------------------------
#define GBK 64                        // halves per K-chunk
#define GSTB 16384                    // one 128x64 fp16 tile in bytes
#define GSTAGE_B (2 * GSTB)           // A+B per stage
#define NSTAGE 3
#define GEMM_SMEM (NSTAGE * GSTAGE_B) // 98304 bytes
#define NKIT (DMODEL / GBK)           // 16

template<bool GATHER_A, bool SCATTER_C, typename OutT>
__device__ __forceinline__ void gemm_f16_body(
    const __half* __restrict__ A, const __half* __restrict__ B,
    const float* __restrict__ bias, OutT* __restrict__ C)
{
    extern __shared__ char smc[];
    const int tid  = threadIdx.x;
    const int lane = tid & 31;
    const int warp = tid >> 5;
    const int wm   = warp >> 2;     // 0..1
    const int wn   = warp & 3;      // 0..3
    const int row0 = blockIdx.y * 128;
    const int col0 = blockIdx.x * 128;

    const uint32_t smbase = (uint32_t)__cvta_generic_to_shared(smc);

    float acc[4][4][4];
#pragma unroll
    for (int mi = 0; mi < 4; mi++)
#pragma unroll
        for (int ni = 0; ni < 4; ni++)
#pragma unroll
            for (int e = 0; e < 4; e++) acc[mi][ni][e] = 0.0f;

    auto load_stage = [&](int s, int k0) {
        uint32_t asb = smbase + (uint32_t)(s * GSTAGE_B);
        uint32_t bsb = asb + GSTB;
#pragma unroll
        for (int i = 0; i < 4; i++) {
            int idx = i * 256 + tid;                // 1024 16B chunks per operand
            int r = idx >> 3, c = idx & 7;
            uint32_t off = (uint32_t)(r * 128 + ((c ^ (r & 7)) << 4));
            int k = k0 + c * 8;                     // halves
            const __half* sa;
            if (GATHER_A) {
                int m = row0 + r;
                sa = A + (size_t)(m >> 11) * BATCH_STRIDE
                       + (size_t)(m & (S_LEN - 1)) * HD
                       + (size_t)(k >> 6) * HEAD_STRIDE + (k & 63);
            } else {
                sa = A + (size_t)(row0 + r) * DMODEL + k;
            }
            cpa(asb + off, sa);
            cpa(bsb + off, B + (size_t)(col0 + r) * DMODEL + k);
        }
    };

    // ldmatrix lane geometry (identical 16B-chunk pairing to the proven tf32
    // version: k16 A-frag = mats {m0-7,k0:8},{m8-15,k0:8},{m0-7,k8:16},{m8-15,k8:16})
    const int g  = lane >> 3;
    const int rl = lane & 7;
    uint32_t arow[4]; int amx[4];
#pragma unroll
    for (int mi = 0; mi < 4; mi++) {
        int m = wm * 64 + mi * 16 + (g & 1) * 8 + rl;
        arow[mi] = (uint32_t)(m * 128);  amx[mi] = m & 7;
    }
    uint32_t brow[2]; int bmx[2];
#pragma unroll
    for (int j = 0; j < 2; j++) {
        int n = wn * 32 + j * 16 + (g >> 1) * 8 + rl;
        brow[j] = (uint32_t)(n * 128);  bmx[j] = n & 7;
    }
    const int akc = g >> 1;
    const int bkc = g & 1;

    auto compute = [&](int s) {
        uint32_t asb = smbase + (uint32_t)(s * GSTAGE_B);
        uint32_t bsb = asb + GSTB;
#pragma unroll
        for (int ks = 0; ks < 4; ks++) {            // 4 k16-steps per 64-chunk
            uint32_t a[4][4], bb[2][4];
#pragma unroll
            for (int mi = 0; mi < 4; mi++)
                ldsm4(a[mi], asb + arow[mi] + (uint32_t)((((2 * ks + akc) ^ amx[mi])) << 4));
#pragma unroll
            for (int j = 0; j < 2; j++)
                ldsm4(bb[j], bsb + brow[j] + (uint32_t)((((2 * ks + bkc) ^ bmx[j])) << 4));
#pragma unroll
            for (int mi = 0; mi < 4; mi++)
#pragma unroll
                for (int j = 0; j < 2; j++) {
                    mma_f16(acc[mi][2 * j],     a[mi], &bb[j][0]);
                    mma_f16(acc[mi][2 * j + 1], a[mi], &bb[j][2]);
                }
        }
    };

    load_stage(0, 0);    cpa_commit();
    load_stage(1, GBK);  cpa_commit();
#pragma unroll 1
    for (int it = 0; it < NKIT; ++it) {
        cpa_wait<1>();
        __syncthreads();
        if (it + 2 < NKIT) load_stage((it + 2) % NSTAGE, (it + 2) * GBK);
        cpa_commit();
        compute(it % NSTAGE);
    }

    // Epilogue: bias + store (fp16-rounded when feeding a later GEMM)
#pragma unroll
    for (int mi = 0; mi < 4; mi++) {
#pragma unroll
        for (int e = 0; e < 2; e++) {
            const int m = row0 + wm * 64 + mi * 16 + (lane >> 2) + e * 8;
#pragma unroll
            for (int ni = 0; ni < 4; ni++) {
                const int n = col0 + wn * 32 + ni * 8 + 2 * (lane & 3);
                float v0 = acc[mi][ni][e * 2 + 0] + bias[n];
                float v1 = acc[mi][ni][e * 2 + 1] + bias[n + 1];
                if (SCATTER_C) {
                    size_t o = (size_t)((m >> 11) * NHEADS + (n >> 6)) * HEAD_STRIDE
                             + (size_t)(m & (S_LEN - 1)) * HD + (n & 63);
                    *(__half2*)((__half*)C + o) = __float22half2_rn(make_float2(v0, v1));
                } else {
                    *(float2*)((float*)C + (size_t)m * DMODEL + n) = make_float2(v0, v1);
                }
            }
        }
    }
}

__global__ __launch_bounds__(256, 2) void qkv_gemm_kernel(
    const float* __restrict__ bq, const float* __restrict__ bk, const float* __restrict__ bv)
{
    const __half* W; const float* b; __half* out;
    if (blockIdx.z == 0)      { W = g_wr[0]; b = bq; out = g_q; }
    else if (blockIdx.z == 1) { W = g_wr[1]; b = bk; out = g_k; }
    else                      { W = g_wr[2]; b = bv; out = g_v; }
    gemm_f16_body<false, true, __half>(g_xr, W, b, out);
}

__global__ __launch_bounds__(256, 2) void out_gemm_kernel(
    const float* __restrict__ bo, float* __restrict__ out)
{
    gemm_f16_body<true, false, float>(g_ctx, g_wr[3], bo, out);
}

// ---------------------------------------------------------------------------
// FP16 flash attention, causal. CTA = 64 queries of one (b,h), 128 threads,
// 4 warps x m16 rows. Q resident in k16 A-fragments (scaled by 1/8, exact).
// K and V both in swizzled smem (128B rows); K via ldmatrix, V via
// ldmatrix.trans. P: S-accum C-frags of adjacent n8 pairs ARE the k16 A-frag
// (FA2 identity) -> no shuffles, no smem round-trip.
// ---------------------------------------------------------------------------
#define ATILE_B 8192                  // 64 x 64 halves
#define ASTG_B (2 * ATILE_B)          // K+V per stage
#define ATTN_SMEM (2 * ASTG_B)        // 32768 bytes

__global__ __launch_bounds__(128, 3) void attn_f16_kernel()
{
    extern __shared__ char smc[];
    const int tid  = threadIdx.x;
    const int lane = tid & 31;
    const int warp = tid >> 5;
    const int qb   = (int)gridDim.x - 1 - (int)blockIdx.x;   // heavy first
    const int bh   = blockIdx.y;

    const size_t base = (size_t)bh * HEAD_STRIDE;
    const __half* Qg = g_q + base + (size_t)qb * 64 * HD;
    const __half* Kg = g_k + base;
    const __half* Vg = g_v + base;
    __half*       Og = g_ctx + base + (size_t)qb * 64 * HD;

    const uint32_t smbase = (uint32_t)__cvta_generic_to_shared(smc);
    const int q3 = lane & 3;
    const int r4 = lane >> 2;
    const int g  = lane >> 3;
    const int rl = lane & 7;

    // Q fragments (4 k16-steps over HD=64), scaled by 1/8 (exact in fp16)
    uint32_t qa[4][4];
    {
        const int r0 = warp * 16 + r4;
        const __half2 sc = __float2half2_rn(0.125f);
#pragma unroll
        for (int s = 0; s < 4; s++) {
            int k = s * 16 + 2 * q3;
            qa[s][0] = h2u(__hmul2(*(const __half2*)(Qg + r0 * HD + k), sc));
            qa[s][1] = h2u(__hmul2(*(const __half2*)(Qg + (r0 + 8) * HD + k), sc));
            qa[s][2] = h2u(__hmul2(*(const __half2*)(Qg + r0 * HD + k + 8), sc));
            qa[s][3] = h2u(__hmul2(*(const __half2*)(Qg + (r0 + 8) * HD + k + 8), sc));
        }
    }

    float o[8][4];
#pragma unroll
    for (int f = 0; f < 8; f++)
#pragma unroll
        for (int e = 0; e < 4; e++) o[f][e] = 0.0f;
    float m0 = -1e30f, m1 = -1e30f, l0 = 0.0f, l1 = 0.0f;

    auto loadKV = [&](int s, int kb) {
        uint32_t kbs = smbase + (uint32_t)(s * ASTG_B);
        uint32_t vbs = kbs + ATILE_B;
        const __half* Kt = Kg + (size_t)kb * 64 * HD;
        const __half* Vt = Vg + (size_t)kb * 64 * HD;
#pragma unroll
        for (int i = 0; i < 4; i++) {
            int idx = i * 128 + tid;           // 512 chunks of 16B per operand
            int r = idx >> 3, c = idx & 7;
            uint32_t off = (uint32_t)(r * 128 + ((c ^ (r & 7)) << 4));
            cpa(kbs + off, Kt + r * HD + c * 8);
            cpa(vbs + off, Vt + r * HD + c * 8);
        }
    };

    // K (non-trans) lane geometry: 4 n16-tiles over 64 kv cols
    uint32_t crow[4]; int cmx[4];
#pragma unroll
    for (int j = 0; j < 4; j++) {
        int c = j * 16 + (g >> 1) * 8 + rl;
        crow[j] = (uint32_t)(c * 128);  cmx[j] = c & 7;
    }
    const int bkc = g & 1;
    // V (trans) lane geometry: row within kv16 group, chunk selects d
    const int vr  = (g & 1) * 8 + rl;      // kv row within 16-group
    const int vmx = vr & 7;
    const int vkc = g >> 1;                // d-chunk offset

    loadKV(0, 0); cpa_commit();

#pragma unroll 1
    for (int kb = 0; kb <= qb; ++kb) {
        if (kb < qb) {
            loadKV((kb + 1) & 1, kb + 1); cpa_commit();
            cpa_wait<1>();
        } else {
            cpa_wait<0>();
        }
        __syncthreads();
        const uint32_t Ksb = smbase + (uint32_t)((kb & 1) * ASTG_B);
        const uint32_t Vsb = Ksb + ATILE_B;

        // S = (Q/8) K^T   (m16 x n64, k16 MMAs)
        float s4[8][4];
#pragma unroll
        for (int f = 0; f < 8; f++)
#pragma unroll
            for (int e = 0; e < 4; e++) s4[f][e] = 0.0f;
#pragma unroll
        for (int ks = 0; ks < 4; ks++) {
#pragma unroll
            for (int j = 0; j < 4; j++) {
                uint32_t kb4[4];
                ldsm4(kb4, Ksb + crow[j] + (uint32_t)((((2 * ks + bkc) ^ cmx[j])) << 4));
                mma_f16(s4[2 * j],     qa[ks], &kb4[0]);
                mma_f16(s4[2 * j + 1], qa[ks], &kb4[2]);
            }
        }

        // Causal mask on diagonal tile
        if (kb == qb) {
            const int rg = warp * 16 + r4;
#pragma unroll
            for (int f = 0; f < 8; f++) {
                const int c0 = f * 8 + 2 * q3;
                if (c0     > rg)     s4[f][0] = -1e30f;
                if (c0 + 1 > rg)     s4[f][1] = -1e30f;
                if (c0     > rg + 8) s4[f][2] = -1e30f;
                if (c0 + 1 > rg + 8) s4[f][3] = -1e30f;
            }
        }

        // Online softmax (2 rows/thread; quad shuffles)
        float mx0 = -1e30f, mx1 = -1e30f;
#pragma unroll
        for (int f = 0; f < 8; f++) {
            mx0 = fmaxf(mx0, fmaxf(s4[f][0], s4[f][1]));
            mx1 = fmaxf(mx1, fmaxf(s4[f][2], s4[f][3]));
        }
        mx0 = fmaxf(mx0, __shfl_xor_sync(0xffffffffu, mx0, 1));
        mx0 = fmaxf(mx0, __shfl_xor_sync(0xffffffffu, mx0, 2));
        mx1 = fmaxf(mx1, __shfl_xor_sync(0xffffffffu, mx1, 1));
        mx1 = fmaxf(mx1, __shfl_xor_sync(0xffffffffu, mx1, 2));
        const float nm0 = fmaxf(m0, mx0), nm1 = fmaxf(m1, mx1);
        const float al0 = __expf(m0 - nm0), al1 = __expf(m1 - nm1);

        // p -> fp16 (the values actually fed to the MMA); sum the rounded ones
        uint32_t ph0[8], ph1[8];
        float rs0 = 0.0f, rs1 = 0.0f;
#pragma unroll
        for (int f = 0; f < 8; f++) {
            __half2 h0 = __float22half2_rn(make_float2(__expf(s4[f][0] - nm0),
                                                       __expf(s4[f][1] - nm0)));
            __half2 h1 = __float22half2_rn(make_float2(__expf(s4[f][2] - nm1),
                                                       __expf(s4[f][3] - nm1)));
            ph0[f] = h2u(h0);  ph1[f] = h2u(h1);
            float2 f0 = __half22float2(h0), f1 = __half22float2(h1);
            rs0 += f0.x + f0.y;
            rs1 += f1.x + f1.y;
        }
        rs0 += __shfl_xor_sync(0xffffffffu, rs0, 1);
        rs0 += __shfl_xor_sync(0xffffffffu, rs0, 2);
        rs1 += __shfl_xor_sync(0xffffffffu, rs1, 1);
        rs1 += __shfl_xor_sync(0xffffffffu, rs1, 2);
        l0 = l0 * al0 + rs0;  l1 = l1 * al1 + rs1;
        m0 = nm0;  m1 = nm1;
#pragma unroll
        for (int f = 0; f < 8; f++) {
            o[f][0] *= al0; o[f][1] *= al0;
            o[f][2] *= al1; o[f][3] *= al1;
        }

        // O += P V : A-frag = C-frag pair (FA2 identity), V via ldmatrix.trans
#pragma unroll
        for (int s = 0; s < 4; s++) {              // kv16-steps
            uint32_t pa[4] = { ph0[2 * s], ph1[2 * s], ph0[2 * s + 1], ph1[2 * s + 1] };
            const uint32_t vrow = (uint32_t)((s * 16 + vr) * 128);
#pragma unroll
            for (int j = 0; j < 4; j++) {          // d16-tiles
                uint32_t vb[4];
                ldsm4t(vb, Vsb + vrow + (uint32_t)((((2 * j + vkc) ^ vmx)) << 4));
                mma_f16(o[2 * j],     pa, &vb[0]);
                mma_f16(o[2 * j + 1], pa, &vb[2]);
            }
        }
        __syncthreads();
    }

    // Epilogue: normalize, round to fp16 (feeds out-proj), store ctx
    const float il0 = 1.0f / l0, il1 = 1.0f / l1;
    const int r0g = warp * 16 + r4;
#pragma unroll
    for (int f = 0; f < 8; f++) {
        const int cc = f * 8 + 2 * q3;
        *(__half2*)(Og + (size_t)r0g * HD + cc) =
            __float22half2_rn(make_float2(o[f][0] * il0, o[f][1] * il0));
        *(__half2*)(Og + (size_t)(r0g + 8) * HD + cc) =
            __float22half2_rn(make_float2(o[f][2] * il1, o[f][3] * il1));
    }
}

// ---------------------------------------------------------------------------
extern "C" void kernel_launch(void* const* d_in, const int* in_sizes, int n_in,
                              void* d_out, int out_size)
{
    (void)in_sizes; (void)n_in; (void)out_size;
    const float* x  = (const float*)d_in[0];
    const float* Wq = (const float*)d_in[1];
    const float* bq = (const float*)d_in[2];
    const float* Wk = (const float*)d_in[3];
    const float* bk = (const float*)d_in[4];
    const float* Wv = (const float*)d_in[5];
    const float* bv = (const float*)d_in[6];
    const float* Wo = (const float*)d_in[7];
    const float* bo = (const float*)d_in[8];
    float* out = (float*)d_out;

    // Host-side, idempotent, capture-safe
    cudaFuncSetAttribute(qkv_gemm_kernel, cudaFuncAttributeMaxDynamicSharedMemorySize, GEMM_SMEM);
    cudaFuncSetAttribute(out_gemm_kernel, cudaFuncAttributeMaxDynamicSharedMemorySize, GEMM_SMEM);
    cudaFuncSetAttribute(attn_f16_kernel, cudaFuncAttributeMaxDynamicSharedMemorySize, ATTN_SMEM);

    // 0) Round x + weights to fp16 scratch copies
    prep_kernel<<<dim3(128, 5), 256>>>(x, Wq, Wk, Wv, Wo);
    // 1) QKV projections -> g_q/g_k/g_v [B,H,S,hd] fp16
    qkv_gemm_kernel<<<dim3(DMODEL / 128, M_ROWS / 128, 3), 256, GEMM_SMEM>>>(bq, bk, bv);
    // 2) Causal flash attention -> g_ctx fp16
    attn_f16_kernel<<<dim3(S_LEN / 64, BHTOT), 128, ATTN_SMEM>>>();
    // 3) Output projection -> d_out fp32
    out_gemm_kernel<<<dim3(DMODEL / 128, M_ROWS / 128), 256, GEMM_SMEM>>>(bo, out);
}